// round 1
// baseline (speedup 1.0000x reference)
#include <cuda_runtime.h>

// FourierBlock: y = irfft( pad_K( (rfft(q)[:, :64]) @ (Wr + i Wi) ) )
// B=8, L=4096, H=8, EIN=EOUT=64, K=64.
//
// Collapsed to:  X = F(128x4096) @ q_b(4096x512)      [64 cos rows, 64 -sin rows]
//                Y' = per-(k,h) complex 64x64 mix, weighted by (k==0?1:2)/L
//                y_b = IBas(4096x128) @ Y'_b(128x512)
//
// DC imaginary part is ignored by c2r irfft; our -sin row for k=0 is 0, which
// reproduces that behavior exactly.

#define L_LEN 4096
#define NB 8
#define NH 8
#define KF 64
#define NC 512          // H * EIN = H * EOUT
#define RSPLIT 8        // split-K factor for the forward GEMM

__device__ float g_fbasis[128 * L_LEN];            // [r][l]   row-major
__device__ float g_ibasis[L_LEN * 128];            // [l][r]   row-major
__device__ float g_Xpart[RSPLIT * NB * 128 * NC];  // [split][b][r][c] partial sums
__device__ float g_Y[NB * 128 * NC];               // [b][r][c]

// ---------------------------------------------------------------------------
// Basis init: both layouts of the same 128x4096 twiddle matrix.
// r < 64  -> cos(2*pi*r*l/L);  r >= 64 -> -sin(2*pi*(r-64)*l/L)
// ---------------------------------------------------------------------------
__global__ __launch_bounds__(256) void init_kernel() {
    int idx = blockIdx.x * blockDim.x + threadIdx.x;
    if (idx >= 128 * L_LEN) return;
    int r = idx >> 12;            // / 4096
    int l = idx & (L_LEN - 1);
    int k = r & 63;
    int m = (k * l) & (L_LEN - 1);
    float s, c;
    sincospif(2.0f * (float)m / 4096.0f, &s, &c);  // exact arg: m / 2048
    float v = (r < 64) ? c : -s;
    g_fbasis[idx] = v;
    g_ibasis[l * 128 + r] = v;
}

// ---------------------------------------------------------------------------
// Generic 128x128-tile SGEMM, C = A @ B (row-major), N fixed at 512.
// MODE 0: A = g_fbasis (128 x 4096), B = q_b, split-K over l into g_Xpart.
// MODE 1: A = g_ibasis (4096 x 128), B = g_Y_b, direct store to out.
// ---------------------------------------------------------------------------
template <int MODE>
__global__ __launch_bounds__(256, 2) void gemm_kernel(const float* __restrict__ Bext,
                                                      float* __restrict__ Cext) {
    constexpr int KD = (MODE == 0) ? L_LEN : 128;
    const int b = blockIdx.z;
    const float* A = (MODE == 0) ? g_fbasis : g_ibasis;
    const float* Bb = (MODE == 0) ? (Bext + (size_t)b * (L_LEN * NC))
                                  : (g_Y + (size_t)b * (128 * NC));
    float* Cb;
    int row0, kbeg, kend;
    if (MODE == 0) {
        row0 = 0;
        const int split = blockIdx.y;
        kbeg = split * (KD / RSPLIT);
        kend = kbeg + KD / RSPLIT;
        Cb = g_Xpart + ((size_t)split * NB + b) * (128 * NC);
    } else {
        row0 = blockIdx.y * 128;
        kbeg = 0;
        kend = KD;
        Cb = Cext + (size_t)b * (L_LEN * NC);
    }
    const int col0 = blockIdx.x * 128;

    __shared__ float As[32][132];   // [kk][row]  (transposed A tile)
    __shared__ float Bs[32][132];   // [kk][col]

    const int tid = threadIdx.x;
    const int tx = tid & 15;
    const int ty = tid >> 4;

    float acc[8][8];
#pragma unroll
    for (int i = 0; i < 8; i++)
#pragma unroll
        for (int j = 0; j < 8; j++) acc[i][j] = 0.0f;

    for (int k0 = kbeg; k0 < kend; k0 += 32) {
#pragma unroll
        for (int e = 0; e < 16; e++) {
            int idx = tid + e * 256;
            int ar = idx >> 5, ak = idx & 31;        // warp reads 32 consecutive k
            As[ak][ar] = A[(size_t)(row0 + ar) * KD + k0 + ak];
        }
#pragma unroll
        for (int e = 0; e < 16; e++) {
            int idx = tid + e * 256;
            int bk = idx >> 7, bc = idx & 127;       // coalesced 128-float rows
            Bs[bk][bc] = Bb[(size_t)(k0 + bk) * NC + col0 + bc];
        }
        __syncthreads();
#pragma unroll
        for (int kk = 0; kk < 32; kk++) {
            float a[8], bv[8];
            *(float4*)&a[0]  = *(const float4*)&As[kk][ty * 4];
            *(float4*)&a[4]  = *(const float4*)&As[kk][64 + ty * 4];
            *(float4*)&bv[0] = *(const float4*)&Bs[kk][tx * 4];
            *(float4*)&bv[4] = *(const float4*)&Bs[kk][64 + tx * 4];
#pragma unroll
            for (int i = 0; i < 8; i++)
#pragma unroll
                for (int j = 0; j < 8; j++) acc[i][j] += a[i] * bv[j];
        }
        __syncthreads();
    }

#pragma unroll
    for (int ih = 0; ih < 2; ih++)
#pragma unroll
        for (int i = 0; i < 4; i++) {
            const int r = row0 + ih * 64 + ty * 4 + i;
            float4 v0 = make_float4(acc[ih * 4 + i][0], acc[ih * 4 + i][1],
                                    acc[ih * 4 + i][2], acc[ih * 4 + i][3]);
            float4 v1 = make_float4(acc[ih * 4 + i][4], acc[ih * 4 + i][5],
                                    acc[ih * 4 + i][6], acc[ih * 4 + i][7]);
            *(float4*)&Cb[(size_t)r * NC + col0 + tx * 4] = v0;
            *(float4*)&Cb[(size_t)r * NC + col0 + 64 + tx * 4] = v1;
        }
}

// ---------------------------------------------------------------------------
// Per-(k,h) complex mix: Y'[b,k,h,o] = w_k * sum_i X[b,k,h,i] * W[k,h,i,o]
// Also folds the split-K reduction of g_Xpart.
// ---------------------------------------------------------------------------
__global__ __launch_bounds__(256) void einsum_kernel(const float* __restrict__ Wr,
                                                     const float* __restrict__ Wi) {
    __shared__ float sWr[64][64];
    __shared__ float sWi[64][64];
    __shared__ float sXr[8][64];
    __shared__ float sXi[8][64];

    const int kh = blockIdx.x;        // k * NH + h
    const int k = kh >> 3;
    const int h = kh & 7;

    const float* wr = Wr + (size_t)kh * 4096;
    const float* wi = Wi + (size_t)kh * 4096;
    for (int e = threadIdx.x; e < 4096; e += 256) {
        sWr[e >> 6][e & 63] = wr[e];
        sWi[e >> 6][e & 63] = wi[e];
    }
    for (int e = threadIdx.x; e < 512; e += 256) {
        const int b = e >> 6, i = e & 63;
        float sr = 0.f, si = 0.f;
        const size_t base = (size_t)b * (128 * NC) + (size_t)k * NC + h * 64 + i;
#pragma unroll
        for (int s = 0; s < RSPLIT; s++) {
            sr += g_Xpart[(size_t)s * (NB * 128 * NC) + base];
            si += g_Xpart[(size_t)s * (NB * 128 * NC) + base + 64 * NC];
        }
        sXr[b][i] = sr;
        sXi[b][i] = si;
    }
    __syncthreads();

    const int o = threadIdx.x & 63;
    const int bg = threadIdx.x >> 6;
    const float w = (k == 0 ? 1.0f : 2.0f) / (float)L_LEN;
    for (int bb = bg; bb < NB; bb += 4) {
        float ar = 0.f, ai = 0.f;
#pragma unroll
        for (int i = 0; i < 64; i++) {
            const float xr = sXr[bb][i], xi = sXi[bb][i];
            const float wrv = sWr[i][o], wiv = sWi[i][o];
            ar += xr * wrv - xi * wiv;
            ai += xr * wiv + xi * wrv;
        }
        g_Y[(size_t)bb * (128 * NC) + (size_t)k * NC + h * 64 + o] = ar * w;
        g_Y[(size_t)bb * (128 * NC) + (size_t)(64 + k) * NC + h * 64 + o] = ai * w;
    }
}

// ---------------------------------------------------------------------------
// inputs (metadata order): q, k, v, W_real, W_imag, mask
// ---------------------------------------------------------------------------
extern "C" void kernel_launch(void* const* d_in, const int* in_sizes, int n_in,
                              void* d_out, int out_size) {
    const float* q  = (const float*)d_in[0];
    const float* Wr = (const float*)d_in[3];
    const float* Wi = (const float*)d_in[4];
    float* out = (float*)d_out;

    init_kernel<<<(128 * L_LEN + 255) / 256, 256>>>();
    gemm_kernel<0><<<dim3(4, RSPLIT, NB), 256>>>(q, nullptr);
    einsum_kernel<<<KF * NH, 256>>>(Wr, Wi);
    gemm_kernel<1><<<dim3(4, L_LEN / 128, NB), 256>>>(nullptr, out);
}

// round 2
// speedup vs baseline: 1.7027x; 1.7027x over previous
#include <cuda_runtime.h>
#include <cuda_bf16.h>

// FourierBlock: y = irfft( pad_K( (rfft(q)[:, :64]) @ (Wr + i Wi) ) )
// Collapsed to two dense GEMMs + tiny complex mix, run on tensor cores with
// bf16 hi/lo 3-way split for fp32-grade accuracy.

#define L_LEN 4096
#define NB 8
#define NH 8
#define KF 64
#define NC 512
#define RSPLIT 8

// ---- scratch (all __device__ globals; no allocs) ----
__device__ __align__(16) __nv_bfloat16 g_fb_h[128 * L_LEN];
__device__ __align__(16) __nv_bfloat16 g_fb_l[128 * L_LEN];
__device__ __align__(16) __nv_bfloat16 g_ib_h[L_LEN * 128];
__device__ __align__(16) __nv_bfloat16 g_ib_l[L_LEN * 128];
__device__ __align__(16) __nv_bfloat16 g_q_h[NB * L_LEN * NC];
__device__ __align__(16) __nv_bfloat16 g_q_l[NB * L_LEN * NC];
__device__ __align__(16) __nv_bfloat16 g_Y_h[NB * 128 * NC];
__device__ __align__(16) __nv_bfloat16 g_Y_l[NB * 128 * NC];
__device__ __align__(16) float g_Xpart[RSPLIT * NB * 128 * NC];

__device__ __forceinline__ void split2(float v, __nv_bfloat16& h, __nv_bfloat16& l) {
    h = __float2bfloat16(v);
    l = __float2bfloat16(v - __bfloat162float(h));
}

// ---------------------------------------------------------------------------
// Basis init: 128x4096 twiddles, hi/lo, both layouts.
// r < 64 -> cos(2*pi*r*l/L);  r >= 64 -> -sin(2*pi*(r-64)*l/L)
// ---------------------------------------------------------------------------
__global__ __launch_bounds__(256) void init_kernel() {
    int idx = blockIdx.x * blockDim.x + threadIdx.x;
    if (idx >= 128 * L_LEN) return;
    int r = idx >> 12;
    int l = idx & (L_LEN - 1);
    int k = r & 63;
    int m = (k * l) & (L_LEN - 1);
    float s, c;
    sincospif(2.0f * (float)m / 4096.0f, &s, &c);
    float v = (r < 64) ? c : -s;
    __nv_bfloat16 h, lo;
    split2(v, h, lo);
    g_fb_h[idx] = h;          g_fb_l[idx] = lo;
    g_ib_h[l * 128 + r] = h;  g_ib_l[l * 128 + r] = lo;
}

// ---------------------------------------------------------------------------
// q fp32 -> bf16 hi/lo
// ---------------------------------------------------------------------------
__global__ __launch_bounds__(256) void conv_kernel(const float4* __restrict__ q) {
    int i = blockIdx.x * blockDim.x + threadIdx.x;  // 4 elements each
    if (i >= NB * L_LEN * NC / 4) return;
    float4 v = q[i];
    __nv_bfloat16 h0, l0, h1, l1, h2, l2, h3, l3;
    split2(v.x, h0, l0); split2(v.y, h1, l1);
    split2(v.z, h2, l2); split2(v.w, h3, l3);
    __nv_bfloat162* qh = (__nv_bfloat162*)g_q_h;
    __nv_bfloat162* ql = (__nv_bfloat162*)g_q_l;
    qh[i * 2] = __nv_bfloat162(h0, h1); qh[i * 2 + 1] = __nv_bfloat162(h2, h3);
    ql[i * 2] = __nv_bfloat162(l0, l1); ql[i * 2 + 1] = __nv_bfloat162(l2, l3);
}

// ---------------------------------------------------------------------------
// MMA GEMM, 128x128 CTA tile, 8 warps (each 64x32), bf16 m16n8k16, 3 passes:
//   pass0 Ah*Bh, pass1 Ah*Bl, pass2 Al*Bh  (all into same fp32 accumulators)
// MODE 0: A = fbasis(128x4096), B = q_b, split-K over l -> g_Xpart partials.
// MODE 1: A = ibasis(4096x128), B = Y_b -> out.
// ---------------------------------------------------------------------------
#define TKC 64
#define A_STRIDE 72              // bf16 elems per smem row (64 + 8 pad)
#define B_STRIDE 136             // (128 + 8 pad)
#define ABYTES (128 * A_STRIDE * 2)   // 18432
#define BBYTES (TKC * B_STRIDE * 2)   // 17408
#define BUFBYTES (ABYTES + BBYTES)    // 35840

#define CP_ASYNC16(dst_u32, src) \
    asm volatile("cp.async.cg.shared.global [%0], [%1], 16;\n" :: "r"(dst_u32), "l"(src))
#define CP_COMMIT() asm volatile("cp.async.commit_group;\n" ::)
#define CP_WAIT1() asm volatile("cp.async.wait_group 1;\n" ::)
#define CP_WAIT0() asm volatile("cp.async.wait_group 0;\n" ::)

template <int MODE>
__global__ __launch_bounds__(256) void mma_gemm(float* __restrict__ Cext) {
    constexpr int KD = (MODE == 0) ? L_LEN : 128;
    constexpr int NCHUNK = (MODE == 0) ? (L_LEN / RSPLIT) / TKC : 128 / TKC; // 8 : 2
    constexpr int NITER = 3 * NCHUNK;

    const int b = blockIdx.z;
    const int col0 = blockIdx.x * 128;
    int row0, kbeg;
    const __nv_bfloat16 *Ah, *Al, *Bh, *Bl;
    float* Cb;
    if (MODE == 0) {
        row0 = 0;
        kbeg = blockIdx.y * (L_LEN / RSPLIT);
        Ah = g_fb_h; Al = g_fb_l;
        Bh = g_q_h + (size_t)b * (L_LEN * NC);
        Bl = g_q_l + (size_t)b * (L_LEN * NC);
        Cb = g_Xpart + ((size_t)blockIdx.y * NB + b) * (128 * NC);
    } else {
        row0 = blockIdx.y * 128;
        kbeg = 0;
        Ah = g_ib_h; Al = g_ib_l;
        Bh = g_Y_h + (size_t)b * (128 * NC);
        Bl = g_Y_l + (size_t)b * (128 * NC);
        Cb = Cext + (size_t)b * (L_LEN * NC);
    }

    extern __shared__ __align__(16) char smem[];
    const unsigned smem_u32 = (unsigned)__cvta_generic_to_shared(smem);
    const int tid = threadIdx.x;
    const int lane = tid & 31, wid = tid >> 5;
    const int wm = wid & 1, wn = wid >> 1;

    float acc[4][4][4];
#pragma unroll
    for (int mi = 0; mi < 4; mi++)
#pragma unroll
        for (int ni = 0; ni < 4; ni++)
#pragma unroll
            for (int r = 0; r < 4; r++) acc[mi][ni][r] = 0.0f;

    auto prefetch = [&](int it) {
        const int pass = it / NCHUNK, ch = it % NCHUNK;
        const int k0 = kbeg + ch * TKC;
        const __nv_bfloat16* Ag = (pass < 2) ? Ah : Al;
        const __nv_bfloat16* Bg = (pass == 1) ? Bl : Bh;
        const unsigned base = smem_u32 + (it & 1) * BUFBYTES;
#pragma unroll
        for (int i = 0; i < 4; i++) {                 // A: 128 x 64, 16B per op
            int idx = tid + i * 256;
            int r = idx >> 3, s8 = idx & 7;
            CP_ASYNC16(base + r * (A_STRIDE * 2) + s8 * 16,
                       Ag + (size_t)(row0 + r) * KD + k0 + s8 * 8);
        }
#pragma unroll
        for (int i = 0; i < 4; i++) {                 // B: 64 x 128
            int idx = tid + i * 256;
            int r = idx >> 4, s8 = idx & 15;
            CP_ASYNC16(base + ABYTES + r * (B_STRIDE * 2) + s8 * 16,
                       Bg + (size_t)(k0 + r) * NC + col0 + s8 * 8);
        }
        CP_COMMIT();
    };

    prefetch(0);

    for (int it = 0; it < NITER; it++) {
        if (it + 1 < NITER) { prefetch(it + 1); CP_WAIT1(); }
        else { CP_WAIT0(); }
        __syncthreads();

        const unsigned base = smem_u32 + (it & 1) * BUFBYTES;
#pragma unroll
        for (int kstep = 0; kstep < TKC / 16; kstep++) {
            unsigned fa[4][4], fb[4][2];
#pragma unroll
            for (int mi = 0; mi < 4; mi++) {
                unsigned addr = base +
                    (unsigned)((wm * 64 + mi * 16 + (lane & 15)) * (A_STRIDE * 2) +
                               kstep * 32 + (lane >> 4) * 16);
                asm volatile("ldmatrix.sync.aligned.m8n8.x4.shared.b16 {%0,%1,%2,%3}, [%4];"
                             : "=r"(fa[mi][0]), "=r"(fa[mi][1]), "=r"(fa[mi][2]), "=r"(fa[mi][3])
                             : "r"(addr));
            }
#pragma unroll
            for (int ni = 0; ni < 4; ni++) {
                unsigned addr = base + ABYTES +
                    (unsigned)((kstep * 16 + (lane & 15)) * (B_STRIDE * 2) +
                               (wn * 32 + ni * 8) * 2);
                asm volatile("ldmatrix.sync.aligned.m8n8.x2.trans.shared.b16 {%0,%1}, [%2];"
                             : "=r"(fb[ni][0]), "=r"(fb[ni][1]) : "r"(addr));
            }
#pragma unroll
            for (int mi = 0; mi < 4; mi++)
#pragma unroll
                for (int ni = 0; ni < 4; ni++)
                    asm volatile(
                        "mma.sync.aligned.m16n8k16.row.col.f32.bf16.bf16.f32 "
                        "{%0,%1,%2,%3}, {%4,%5,%6,%7}, {%8,%9}, {%0,%1,%2,%3};"
                        : "+f"(acc[mi][ni][0]), "+f"(acc[mi][ni][1]),
                          "+f"(acc[mi][ni][2]), "+f"(acc[mi][ni][3])
                        : "r"(fa[mi][0]), "r"(fa[mi][1]), "r"(fa[mi][2]), "r"(fa[mi][3]),
                          "r"(fb[ni][0]), "r"(fb[ni][1]));
        }
        __syncthreads();
    }

    const int g = lane >> 2, tig = lane & 3;
#pragma unroll
    for (int mi = 0; mi < 4; mi++)
#pragma unroll
        for (int ni = 0; ni < 4; ni++) {
            int r = row0 + wm * 64 + mi * 16 + g;
            int c = col0 + wn * 32 + ni * 8 + tig * 2;
            *(float2*)&Cb[(size_t)r * NC + c] = make_float2(acc[mi][ni][0], acc[mi][ni][1]);
            *(float2*)&Cb[(size_t)(r + 8) * NC + c] = make_float2(acc[mi][ni][2], acc[mi][ni][3]);
        }
}

// ---------------------------------------------------------------------------
// Split-K reduce + per-(k,h) complex mix; emits Y as bf16 hi/lo.
// ---------------------------------------------------------------------------
__global__ __launch_bounds__(256) void einsum_kernel(const float* __restrict__ Wr,
                                                     const float* __restrict__ Wi) {
    __shared__ float sWr[64][64];
    __shared__ float sWi[64][64];
    __shared__ float sXr[8][64];
    __shared__ float sXi[8][64];

    const int kh = blockIdx.x;
    const int k = kh >> 3;
    const int h = kh & 7;

    const float* wr = Wr + (size_t)kh * 4096;
    const float* wi = Wi + (size_t)kh * 4096;
    for (int e = threadIdx.x; e < 4096; e += 256) {
        sWr[e >> 6][e & 63] = wr[e];
        sWi[e >> 6][e & 63] = wi[e];
    }
    for (int e = threadIdx.x; e < 512; e += 256) {
        const int b = e >> 6, i = e & 63;
        float sr = 0.f, si = 0.f;
        const size_t base = (size_t)b * (128 * NC) + (size_t)k * NC + h * 64 + i;
#pragma unroll
        for (int s = 0; s < RSPLIT; s++) {
            sr += g_Xpart[(size_t)s * (NB * 128 * NC) + base];
            si += g_Xpart[(size_t)s * (NB * 128 * NC) + base + 64 * NC];
        }
        sXr[b][i] = sr;
        sXi[b][i] = si;
    }
    __syncthreads();

    const int o = threadIdx.x & 63;
    const int bg = threadIdx.x >> 6;
    const float w = (k == 0 ? 1.0f : 2.0f) / (float)L_LEN;
    for (int bb = bg; bb < NB; bb += 4) {
        float ar = 0.f, ai = 0.f;
#pragma unroll
        for (int i = 0; i < 64; i++) {
            const float xr = sXr[bb][i], xi = sXi[bb][i];
            const float wrv = sWr[i][o], wiv = sWi[i][o];
            ar += xr * wrv - xi * wiv;
            ai += xr * wiv + xi * wrv;
        }
        const size_t pr = (size_t)bb * (128 * NC) + (size_t)k * NC + h * 64 + o;
        const size_t pi = (size_t)bb * (128 * NC) + (size_t)(64 + k) * NC + h * 64 + o;
        __nv_bfloat16 hh, ll;
        split2(ar * w, hh, ll);
        g_Y_h[pr] = hh; g_Y_l[pr] = ll;
        split2(ai * w, hh, ll);
        g_Y_h[pi] = hh; g_Y_l[pi] = ll;
    }
}

// ---------------------------------------------------------------------------
// inputs (metadata order): q, k, v, W_real, W_imag, mask
// ---------------------------------------------------------------------------
extern "C" void kernel_launch(void* const* d_in, const int* in_sizes, int n_in,
                              void* d_out, int out_size) {
    const float* q  = (const float*)d_in[0];
    const float* Wr = (const float*)d_in[3];
    const float* Wi = (const float*)d_in[4];
    float* out = (float*)d_out;

    static bool attr_done = false;
    if (!attr_done) {
        cudaFuncSetAttribute(mma_gemm<0>, cudaFuncAttributeMaxDynamicSharedMemorySize,
                             2 * BUFBYTES);
        cudaFuncSetAttribute(mma_gemm<1>, cudaFuncAttributeMaxDynamicSharedMemorySize,
                             2 * BUFBYTES);
        attr_done = true;
    }

    init_kernel<<<(128 * L_LEN + 255) / 256, 256>>>();
    conv_kernel<<<(NB * L_LEN * NC / 4 + 255) / 256, 256>>>((const float4*)q);
    mma_gemm<0><<<dim3(4, RSPLIT, NB), 256, 2 * BUFBYTES>>>(nullptr);
    einsum_kernel<<<KF * NH, 256>>>(Wr, Wi);
    mma_gemm<1><<<dim3(4, L_LEN / 128, NB), 256, 2 * BUFBYTES>>>(out);
}

// round 4
// speedup vs baseline: 2.1119x; 1.2403x over previous
#include <cuda_runtime.h>
#include <cuda_bf16.h>

// FourierBlock: y = irfft( pad_K( (rfft(q)[:, :64]) @ (Wr + i Wi) ) )
// Two dense GEMMs on tensor cores (bf16 hi/lo 3-term split, pass-fused) plus
// a small complex-mix kernel.

#define L_LEN 4096
#define NB 8
#define NH 8
#define KF 64
#define NC 512
#define RSPLIT 8

// ---- scratch (all __device__ globals; no allocs) ----
__device__ __align__(16) __nv_bfloat16 g_fb_h[128 * L_LEN];
__device__ __align__(16) __nv_bfloat16 g_fb_l[128 * L_LEN];
__device__ __align__(16) __nv_bfloat16 g_ib_h[L_LEN * 128];
__device__ __align__(16) __nv_bfloat16 g_ib_l[L_LEN * 128];
__device__ __align__(16) __nv_bfloat16 g_q_h[NB * L_LEN * NC];
__device__ __align__(16) __nv_bfloat16 g_q_l[NB * L_LEN * NC];
__device__ __align__(16) __nv_bfloat16 g_Y_h[NB * 128 * NC];
__device__ __align__(16) __nv_bfloat16 g_Y_l[NB * 128 * NC];
__device__ __align__(16) float g_Xpart[RSPLIT * NB * 128 * NC];

__device__ __forceinline__ void split2(float v, __nv_bfloat16& h, __nv_bfloat16& l) {
    h = __float2bfloat16(v);
    l = __float2bfloat16(v - __bfloat162float(h));
}

// ---------------------------------------------------------------------------
// Basis init: 128x4096 twiddles, hi/lo, both layouts.
// ---------------------------------------------------------------------------
__global__ __launch_bounds__(256) void init_kernel() {
    int idx = blockIdx.x * blockDim.x + threadIdx.x;
    if (idx >= 128 * L_LEN) return;
    int r = idx >> 12;
    int l = idx & (L_LEN - 1);
    int k = r & 63;
    int m = (k * l) & (L_LEN - 1);
    float s, c;
    sincospif(2.0f * (float)m / 4096.0f, &s, &c);
    float v = (r < 64) ? c : -s;
    __nv_bfloat16 h, lo;
    split2(v, h, lo);
    g_fb_h[idx] = h;          g_fb_l[idx] = lo;
    g_ib_h[l * 128 + r] = h;  g_ib_l[l * 128 + r] = lo;
}

// ---------------------------------------------------------------------------
// q fp32 -> bf16 hi/lo
// ---------------------------------------------------------------------------
__global__ __launch_bounds__(256) void conv_kernel(const float4* __restrict__ q) {
    int i = blockIdx.x * blockDim.x + threadIdx.x;
    if (i >= NB * L_LEN * NC / 4) return;
    float4 v = q[i];
    __nv_bfloat16 h0, l0, h1, l1, h2, l2, h3, l3;
    split2(v.x, h0, l0); split2(v.y, h1, l1);
    split2(v.z, h2, l2); split2(v.w, h3, l3);
    __nv_bfloat162* qh = (__nv_bfloat162*)g_q_h;
    __nv_bfloat162* ql = (__nv_bfloat162*)g_q_l;
    qh[i * 2] = __nv_bfloat162(h0, h1); qh[i * 2 + 1] = __nv_bfloat162(h2, h3);
    ql[i * 2] = __nv_bfloat162(l0, l1); ql[i * 2 + 1] = __nv_bfloat162(l2, l3);
}

// ---------------------------------------------------------------------------
// Pass-fused MMA GEMM, 128x128 CTA tile, 8 warps (each 64x32), m16n8k16.
// Per k-chunk: stage Ah, Al, Bh, Bl; issue Ah*Bh + Ah*Bl + Al*Bh.
// MODE 0: A = fbasis(128x4096), B = q_b, split-K over l -> g_Xpart partials.
// MODE 1: A = ibasis(4096x128), B = Y_b -> out.
// ---------------------------------------------------------------------------
#define TKC 64
#define ASTR 72                      // bf16 elems per smem row (64 + 8 pad)
#define BSTR 136                     // (128 + 8 pad)
#define ATILE (128 * ASTR * 2)       // 18432 bytes
#define BTILE (TKC * BSTR * 2)       // 17408 bytes
#define BUFBYTES (2 * ATILE + 2 * BTILE)  // 71680

#define CP_ASYNC16(dst_u32, src) \
    asm volatile("cp.async.cg.shared.global [%0], [%1], 16;\n" :: "r"(dst_u32), "l"(src))
#define CP_COMMIT() asm volatile("cp.async.commit_group;\n" ::)
#define CP_WAIT1() asm volatile("cp.async.wait_group 1;\n" ::)
#define CP_WAIT0() asm volatile("cp.async.wait_group 0;\n" ::)

template <int MODE>
__global__ __launch_bounds__(256) void mma_gemm(float* __restrict__ Cext) {
    constexpr int KD = (MODE == 0) ? L_LEN : 128;
    constexpr int NCHUNK = (MODE == 0) ? (L_LEN / RSPLIT) / TKC : 128 / TKC; // 8 : 2

    const int b = blockIdx.z;
    const int col0 = blockIdx.x * 128;
    int row0, kbeg;
    const __nv_bfloat16 *Ah, *Al, *Bh, *Bl;
    float* Cb;
    if (MODE == 0) {
        row0 = 0;
        kbeg = blockIdx.y * (L_LEN / RSPLIT);
        Ah = g_fb_h; Al = g_fb_l;
        Bh = g_q_h + (size_t)b * (L_LEN * NC);
        Bl = g_q_l + (size_t)b * (L_LEN * NC);
        Cb = g_Xpart + ((size_t)blockIdx.y * NB + b) * (128 * NC);
    } else {
        row0 = blockIdx.y * 128;
        kbeg = 0;
        Ah = g_ib_h; Al = g_ib_l;
        Bh = g_Y_h + (size_t)b * (128 * NC);
        Bl = g_Y_l + (size_t)b * (128 * NC);
        Cb = Cext + (size_t)b * (L_LEN * NC);
    }

    extern __shared__ __align__(16) char smem[];
    const unsigned smem_u32 = (unsigned)__cvta_generic_to_shared(smem);
    const int tid = threadIdx.x;
    const int lane = tid & 31, wid = tid >> 5;
    const int wm = wid & 1, wn = wid >> 1;

    float acc[4][4][4];
#pragma unroll
    for (int mi = 0; mi < 4; mi++)
#pragma unroll
        for (int ni = 0; ni < 4; ni++)
#pragma unroll
            for (int r = 0; r < 4; r++) acc[mi][ni][r] = 0.0f;

    auto prefetch = [&](int ch) {
        const int k0 = kbeg + ch * TKC;
        const unsigned base = smem_u32 + (ch & 1) * BUFBYTES;
#pragma unroll
        for (int i = 0; i < 4; i++) {                 // A tiles: 128 x 64 each
            int idx = tid + i * 256;
            int r = idx >> 3, s8 = idx & 7;
            const size_t off = (size_t)(row0 + r) * KD + k0 + s8 * 8;
            CP_ASYNC16(base + r * (ASTR * 2) + s8 * 16, Ah + off);
            CP_ASYNC16(base + ATILE + r * (ASTR * 2) + s8 * 16, Al + off);
        }
#pragma unroll
        for (int i = 0; i < 4; i++) {                 // B tiles: 64 x 128 each
            int idx = tid + i * 256;
            int r = idx >> 4, s8 = idx & 15;
            const size_t off = (size_t)(k0 + r) * NC + col0 + s8 * 8;
            CP_ASYNC16(base + 2 * ATILE + r * (BSTR * 2) + s8 * 16, Bh + off);
            CP_ASYNC16(base + 2 * ATILE + BTILE + r * (BSTR * 2) + s8 * 16, Bl + off);
        }
        CP_COMMIT();
    };

    prefetch(0);

    for (int it = 0; it < NCHUNK; it++) {
        if (it + 1 < NCHUNK) { prefetch(it + 1); CP_WAIT1(); }
        else { CP_WAIT0(); }
        __syncthreads();

        const unsigned base = smem_u32 + (it & 1) * BUFBYTES;
#pragma unroll
        for (int kstep = 0; kstep < TKC / 16; kstep++) {
            unsigned fah[4][4], fal[4][4], fbh[4][2], fbl[4][2];
#pragma unroll
            for (int mi = 0; mi < 4; mi++) {
                unsigned addr = base +
                    (unsigned)((wm * 64 + mi * 16 + (lane & 15)) * (ASTR * 2) +
                               kstep * 32 + (lane >> 4) * 16);
                asm volatile("ldmatrix.sync.aligned.m8n8.x4.shared.b16 {%0,%1,%2,%3}, [%4];"
                             : "=r"(fah[mi][0]), "=r"(fah[mi][1]), "=r"(fah[mi][2]), "=r"(fah[mi][3])
                             : "r"(addr));
                asm volatile("ldmatrix.sync.aligned.m8n8.x4.shared.b16 {%0,%1,%2,%3}, [%4];"
                             : "=r"(fal[mi][0]), "=r"(fal[mi][1]), "=r"(fal[mi][2]), "=r"(fal[mi][3])
                             : "r"(addr + ATILE));
            }
#pragma unroll
            for (int ni = 0; ni < 4; ni++) {
                unsigned addr = base + 2 * ATILE +
                    (unsigned)((kstep * 16 + (lane & 15)) * (BSTR * 2) +
                               (wn * 32 + ni * 8) * 2);
                asm volatile("ldmatrix.sync.aligned.m8n8.x2.trans.shared.b16 {%0,%1}, [%2];"
                             : "=r"(fbh[ni][0]), "=r"(fbh[ni][1]) : "r"(addr));
                asm volatile("ldmatrix.sync.aligned.m8n8.x2.trans.shared.b16 {%0,%1}, [%2];"
                             : "=r"(fbl[ni][0]), "=r"(fbl[ni][1]) : "r"(addr + BTILE));
            }
#pragma unroll
            for (int mi = 0; mi < 4; mi++)
#pragma unroll
                for (int ni = 0; ni < 4; ni++) {
#define MMA_BF16(A0,A1,A2,A3,B0,B1)                                            \
    asm volatile("mma.sync.aligned.m16n8k16.row.col.f32.bf16.bf16.f32 "        \
                 "{%0,%1,%2,%3}, {%4,%5,%6,%7}, {%8,%9}, {%0,%1,%2,%3};"       \
                 : "+f"(acc[mi][ni][0]), "+f"(acc[mi][ni][1]),                 \
                   "+f"(acc[mi][ni][2]), "+f"(acc[mi][ni][3])                  \
                 : "r"(A0), "r"(A1), "r"(A2), "r"(A3), "r"(B0), "r"(B1))
                    MMA_BF16(fah[mi][0], fah[mi][1], fah[mi][2], fah[mi][3],
                             fbh[ni][0], fbh[ni][1]);
                    MMA_BF16(fah[mi][0], fah[mi][1], fah[mi][2], fah[mi][3],
                             fbl[ni][0], fbl[ni][1]);
                    MMA_BF16(fal[mi][0], fal[mi][1], fal[mi][2], fal[mi][3],
                             fbh[ni][0], fbh[ni][1]);
#undef MMA_BF16
                }
        }
        __syncthreads();
    }

    const int g = lane >> 2, tig = lane & 3;
#pragma unroll
    for (int mi = 0; mi < 4; mi++)
#pragma unroll
        for (int ni = 0; ni < 4; ni++) {
            int r = row0 + wm * 64 + mi * 16 + g;
            int c = col0 + wn * 32 + ni * 8 + tig * 2;
            *(float2*)&Cb[(size_t)r * NC + c] = make_float2(acc[mi][ni][0], acc[mi][ni][1]);
            *(float2*)&Cb[(size_t)(r + 8) * NC + c] = make_float2(acc[mi][ni][2], acc[mi][ni][3]);
        }
}

// ---------------------------------------------------------------------------
// Split-K reduce + per-(k,h) complex mix; 512 threads, one (b,o) per thread.
// ---------------------------------------------------------------------------
__global__ __launch_bounds__(512) void einsum_kernel(const float* __restrict__ Wr,
                                                     const float* __restrict__ Wi) {
    __shared__ float sWr[64][64];
    __shared__ float sWi[64][64];
    __shared__ float sXr[8][64];
    __shared__ float sXi[8][64];

    const int kh = blockIdx.x;
    const int k = kh >> 3;
    const int h = kh & 7;
    const int tid = threadIdx.x;

    const float4* wr4 = (const float4*)(Wr + (size_t)kh * 4096);
    const float4* wi4 = (const float4*)(Wi + (size_t)kh * 4096);
    float4* sWr4 = (float4*)sWr;
    float4* sWi4 = (float4*)sWi;
#pragma unroll
    for (int e = 0; e < 2; e++) {
        sWr4[tid + e * 512] = wr4[tid + e * 512];
        sWi4[tid + e * 512] = wi4[tid + e * 512];
    }
    {
        const int b = tid >> 6, i = tid & 63;
        float sr = 0.f, si = 0.f;
        const float* p = g_Xpart + (size_t)b * (128 * NC) + (size_t)k * NC + h * 64 + i;
#pragma unroll
        for (int s = 0; s < RSPLIT; s++) {
            sr += p[0];
            si += p[64 * NC];
            p += (size_t)NB * 128 * NC;
        }
        sXr[b][i] = sr;
        sXi[b][i] = si;
    }
    __syncthreads();

    const int o = tid & 63;
    const int bb = tid >> 6;
    const float w = (k == 0 ? 1.0f : 2.0f) / (float)L_LEN;
    float ar = 0.f, ai = 0.f;
#pragma unroll
    for (int i = 0; i < 64; i++) {
        const float xr = sXr[bb][i], xi = sXi[bb][i];
        const float wrv = sWr[i][o], wiv = sWi[i][o];
        ar += xr * wrv - xi * wiv;
        ai += xr * wiv + xi * wrv;
    }
    const size_t pr = (size_t)bb * (128 * NC) + (size_t)k * NC + h * 64 + o;
    const size_t pi = (size_t)bb * (128 * NC) + (size_t)(64 + k) * NC + h * 64 + o;
    __nv_bfloat16 hh, ll;
    split2(ar * w, hh, ll);
    g_Y_h[pr] = hh; g_Y_l[pr] = ll;
    split2(ai * w, hh, ll);
    g_Y_h[pi] = hh; g_Y_l[pi] = ll;
}

// ---------------------------------------------------------------------------
// inputs (metadata order): q, k, v, W_real, W_imag, mask
// ---------------------------------------------------------------------------
extern "C" void kernel_launch(void* const* d_in, const int* in_sizes, int n_in,
                              void* d_out, int out_size) {
    const float* q  = (const float*)d_in[0];
    const float* Wr = (const float*)d_in[3];
    const float* Wi = (const float*)d_in[4];
    float* out = (float*)d_out;

    static bool attr_done = false;
    if (!attr_done) {
        cudaFuncSetAttribute(mma_gemm<0>, cudaFuncAttributeMaxDynamicSharedMemorySize,
                             2 * BUFBYTES);
        cudaFuncSetAttribute(mma_gemm<1>, cudaFuncAttributeMaxDynamicSharedMemorySize,
                             2 * BUFBYTES);
        attr_done = true;
    }

    init_kernel<<<(128 * L_LEN + 255) / 256, 256>>>();
    conv_kernel<<<(NB * L_LEN * NC / 4 + 255) / 256, 256>>>((const float4*)q);
    mma_gemm<0><<<dim3(4, RSPLIT, NB), 256, 2 * BUFBYTES>>>(nullptr);
    einsum_kernel<<<KF * NH, 512>>>(Wr, Wi);
    mma_gemm<1><<<dim3(4, L_LEN / 128, NB), 256, 2 * BUFBYTES>>>(out);
}

// round 5
// speedup vs baseline: 2.5410x; 1.2032x over previous
#include <cuda_runtime.h>
#include <cuda_bf16.h>

// FourierBlock: y = irfft( pad_K( (rfft(q)[:, :64]) @ (Wr + i Wi) ) )
// Two dense GEMMs on tensor cores (bf16 hi/lo 3-term split, pass-fused) plus
// a small complex-mix kernel. Forward GEMM converts fp32 q to bf16 hi/lo
// in-register while staging to smem (no separate conversion pass).

#define L_LEN 4096
#define NB 8
#define NH 8
#define KF 64
#define NC 512
#define RSPLIT 4

// ---- scratch (all __device__ globals; no allocs) ----
__device__ __align__(16) __nv_bfloat16 g_fb_h[128 * L_LEN];
__device__ __align__(16) __nv_bfloat16 g_fb_l[128 * L_LEN];
__device__ __align__(16) __nv_bfloat16 g_ib_h[L_LEN * 128];
__device__ __align__(16) __nv_bfloat16 g_ib_l[L_LEN * 128];
__device__ __align__(16) __nv_bfloat16 g_Y_h[NB * 128 * NC];
__device__ __align__(16) __nv_bfloat16 g_Y_l[NB * 128 * NC];
__device__ __align__(16) float g_Xpart[RSPLIT * NB * 128 * NC];

__device__ __forceinline__ void split2(float v, __nv_bfloat16& h, __nv_bfloat16& l) {
    h = __float2bfloat16(v);
    l = __float2bfloat16(v - __bfloat162float(h));
}

// ---------------------------------------------------------------------------
// Basis init: 128x4096 twiddles, hi/lo, both layouts.
// ---------------------------------------------------------------------------
__global__ __launch_bounds__(256) void init_kernel() {
    int idx = blockIdx.x * blockDim.x + threadIdx.x;
    if (idx >= 128 * L_LEN) return;
    int r = idx >> 12;
    int l = idx & (L_LEN - 1);
    int k = r & 63;
    int m = (k * l) & (L_LEN - 1);
    float s, c;
    sincospif(2.0f * (float)m / 4096.0f, &s, &c);
    float v = (r < 64) ? c : -s;
    __nv_bfloat16 h, lo;
    split2(v, h, lo);
    g_fb_h[idx] = h;          g_fb_l[idx] = lo;
    g_ib_h[l * 128 + r] = h;  g_ib_l[l * 128 + r] = lo;
}

// ---------------------------------------------------------------------------
// Pass-fused MMA GEMM, 128x128 CTA tile, 8 warps (each 64x32), m16n8k16.
// Per k-chunk: stage Ah, Al, Bh, Bl; issue Ah*Bh + Ah*Bl + Al*Bh.
// MODE 0: A = fbasis(128x4096), B = fp32 q_b (converted in-flight),
//         split-K over l -> g_Xpart partials.
// MODE 1: A = ibasis(4096x128), B = Y_b (bf16 hi/lo via cp.async) -> out.
// ---------------------------------------------------------------------------
#define TKC 64
#define ASTR 72                      // bf16 elems per smem row (64 + 8 pad)
#define BSTR 136                     // (128 + 8 pad)
#define ATILE (128 * ASTR * 2)       // 18432 bytes
#define BTILE (TKC * BSTR * 2)       // 17408 bytes
#define BUFBYTES (2 * ATILE + 2 * BTILE)  // 71680

#define CP_ASYNC16(dst_u32, src) \
    asm volatile("cp.async.cg.shared.global [%0], [%1], 16;\n" :: "r"(dst_u32), "l"(src))
#define CP_COMMIT() asm volatile("cp.async.commit_group;\n" ::)
#define CP_WAIT1() asm volatile("cp.async.wait_group 1;\n" ::)
#define CP_WAIT0() asm volatile("cp.async.wait_group 0;\n" ::)

template <int MODE>
__global__ __launch_bounds__(256) void mma_gemm(const float* __restrict__ Bf32,
                                                float* __restrict__ Cext) {
    constexpr int KD = (MODE == 0) ? L_LEN : 128;
    constexpr int NCHUNK = (MODE == 0) ? (L_LEN / RSPLIT) / TKC : 128 / TKC; // 16 : 2

    const int b = blockIdx.z;
    const int col0 = blockIdx.x * 128;
    int row0, kbeg;
    const __nv_bfloat16 *Ah, *Al, *Bh = nullptr, *Bl = nullptr;
    const float* Bq = nullptr;
    float* Cb;
    if (MODE == 0) {
        row0 = 0;
        kbeg = blockIdx.y * (L_LEN / RSPLIT);
        Ah = g_fb_h; Al = g_fb_l;
        Bq = Bf32 + (size_t)b * (L_LEN * NC);
        Cb = g_Xpart + ((size_t)blockIdx.y * NB + b) * (128 * NC);
    } else {
        row0 = blockIdx.y * 128;
        kbeg = 0;
        Ah = g_ib_h; Al = g_ib_l;
        Bh = g_Y_h + (size_t)b * (128 * NC);
        Bl = g_Y_l + (size_t)b * (128 * NC);
        Cb = Cext + (size_t)b * (L_LEN * NC);
    }

    extern __shared__ __align__(16) char smem[];
    const unsigned smem_u32 = (unsigned)__cvta_generic_to_shared(smem);
    const int tid = threadIdx.x;
    const int lane = tid & 31, wid = tid >> 5;
    const int wm = wid & 1, wn = wid >> 1;

    float acc[4][4][4];
#pragma unroll
    for (int mi = 0; mi < 4; mi++)
#pragma unroll
        for (int ni = 0; ni < 4; ni++)
#pragma unroll
            for (int r = 0; r < 4; r++) acc[mi][ni][r] = 0.0f;

    // A tiles via cp.async (both modes); MODE 1 also stages B via cp.async.
    auto prefetch = [&](int ch) {
        const int k0 = kbeg + ch * TKC;
        const unsigned base = smem_u32 + (ch & 1) * BUFBYTES;
#pragma unroll
        for (int i = 0; i < 4; i++) {                 // A tiles: 128 x 64 each
            int idx = tid + i * 256;
            int r = idx >> 3, s8 = idx & 7;
            const size_t off = (size_t)(row0 + r) * KD + k0 + s8 * 8;
            CP_ASYNC16(base + r * (ASTR * 2) + s8 * 16, Ah + off);
            CP_ASYNC16(base + ATILE + r * (ASTR * 2) + s8 * 16, Al + off);
        }
        if (MODE == 1) {
#pragma unroll
            for (int i = 0; i < 4; i++) {             // B tiles: 64 x 128 each
                int idx = tid + i * 256;
                int r = idx >> 4, s8 = idx & 15;
                const size_t off = (size_t)(k0 + r) * NC + col0 + s8 * 8;
                CP_ASYNC16(base + 2 * ATILE + r * (BSTR * 2) + s8 * 16, Bh + off);
                CP_ASYNC16(base + 2 * ATILE + BTILE + r * (BSTR * 2) + s8 * 16, Bl + off);
            }
        }
        CP_COMMIT();
    };

    // MODE 0: B fp32 register staging + in-flight bf16 split.
    float4 breg[8];
    auto ldgB = [&](int ch) {
        const int k0 = kbeg + ch * TKC;
#pragma unroll
        for (int i = 0; i < 8; i++) {
            int idx = tid + i * 256;
            int r = idx >> 5, c4 = idx & 31;          // 64 rows x 32 float4 segs
            breg[i] = *(const float4*)(Bq + (size_t)(k0 + r) * NC + col0 + c4 * 4);
        }
    };
    auto stsB = [&](int ch) {
        char* base = smem + (ch & 1) * BUFBYTES + 2 * ATILE;
#pragma unroll
        for (int i = 0; i < 8; i++) {
            int idx = tid + i * 256;
            int r = idx >> 5, c4 = idx & 31;
            __nv_bfloat16 h0, l0, h1, l1, h2, l2, h3, l3;
            split2(breg[i].x, h0, l0); split2(breg[i].y, h1, l1);
            split2(breg[i].z, h2, l2); split2(breg[i].w, h3, l3);
            const int off = r * (BSTR * 2) + c4 * 8;
            __nv_bfloat162* ph = (__nv_bfloat162*)(base + off);
            __nv_bfloat162* pl = (__nv_bfloat162*)(base + BTILE + off);
            ph[0] = __nv_bfloat162(h0, h1); ph[1] = __nv_bfloat162(h2, h3);
            pl[0] = __nv_bfloat162(l0, l1); pl[1] = __nv_bfloat162(l2, l3);
        }
    };

    if (MODE == 0) ldgB(0);
    prefetch(0);

    for (int it = 0; it < NCHUNK; it++) {
        if (MODE == 0) stsB(it);
        if (it + 1 < NCHUNK) {
            if (MODE == 0) ldgB(it + 1);
            prefetch(it + 1);
            CP_WAIT1();
        } else {
            CP_WAIT0();
        }
        __syncthreads();

        const unsigned base = smem_u32 + (it & 1) * BUFBYTES;
#pragma unroll
        for (int kstep = 0; kstep < TKC / 16; kstep++) {
            unsigned fah[4][4], fal[4][4], fbh[4][2], fbl[4][2];
#pragma unroll
            for (int mi = 0; mi < 4; mi++) {
                unsigned addr = base +
                    (unsigned)((wm * 64 + mi * 16 + (lane & 15)) * (ASTR * 2) +
                               kstep * 32 + (lane >> 4) * 16);
                asm volatile("ldmatrix.sync.aligned.m8n8.x4.shared.b16 {%0,%1,%2,%3}, [%4];"
                             : "=r"(fah[mi][0]), "=r"(fah[mi][1]), "=r"(fah[mi][2]), "=r"(fah[mi][3])
                             : "r"(addr));
                asm volatile("ldmatrix.sync.aligned.m8n8.x4.shared.b16 {%0,%1,%2,%3}, [%4];"
                             : "=r"(fal[mi][0]), "=r"(fal[mi][1]), "=r"(fal[mi][2]), "=r"(fal[mi][3])
                             : "r"(addr + ATILE));
            }
#pragma unroll
            for (int ni = 0; ni < 4; ni++) {
                unsigned addr = base + 2 * ATILE +
                    (unsigned)((kstep * 16 + (lane & 15)) * (BSTR * 2) +
                               (wn * 32 + ni * 8) * 2);
                asm volatile("ldmatrix.sync.aligned.m8n8.x2.trans.shared.b16 {%0,%1}, [%2];"
                             : "=r"(fbh[ni][0]), "=r"(fbh[ni][1]) : "r"(addr));
                asm volatile("ldmatrix.sync.aligned.m8n8.x2.trans.shared.b16 {%0,%1}, [%2];"
                             : "=r"(fbl[ni][0]), "=r"(fbl[ni][1]) : "r"(addr + BTILE));
            }
#pragma unroll
            for (int mi = 0; mi < 4; mi++)
#pragma unroll
                for (int ni = 0; ni < 4; ni++) {
#define MMA_BF16(A0,A1,A2,A3,B0,B1)                                            \
    asm volatile("mma.sync.aligned.m16n8k16.row.col.f32.bf16.bf16.f32 "        \
                 "{%0,%1,%2,%3}, {%4,%5,%6,%7}, {%8,%9}, {%0,%1,%2,%3};"       \
                 : "+f"(acc[mi][ni][0]), "+f"(acc[mi][ni][1]),                 \
                   "+f"(acc[mi][ni][2]), "+f"(acc[mi][ni][3])                  \
                 : "r"(A0), "r"(A1), "r"(A2), "r"(A3), "r"(B0), "r"(B1))
                    MMA_BF16(fah[mi][0], fah[mi][1], fah[mi][2], fah[mi][3],
                             fbh[ni][0], fbh[ni][1]);
                    MMA_BF16(fah[mi][0], fah[mi][1], fah[mi][2], fah[mi][3],
                             fbl[ni][0], fbl[ni][1]);
                    MMA_BF16(fal[mi][0], fal[mi][1], fal[mi][2], fal[mi][3],
                             fbh[ni][0], fbh[ni][1]);
#undef MMA_BF16
                }
        }
        __syncthreads();
    }

    const int g = lane >> 2, tig = lane & 3;
#pragma unroll
    for (int mi = 0; mi < 4; mi++)
#pragma unroll
        for (int ni = 0; ni < 4; ni++) {
            int r = row0 + wm * 64 + mi * 16 + g;
            int c = col0 + wn * 32 + ni * 8 + tig * 2;
            *(float2*)&Cb[(size_t)r * NC + c] = make_float2(acc[mi][ni][0], acc[mi][ni][1]);
            *(float2*)&Cb[(size_t)(r + 8) * NC + c] = make_float2(acc[mi][ni][2], acc[mi][ni][3]);
        }
}

// ---------------------------------------------------------------------------
// Split-K reduce + per-(k,h) complex mix; 512 threads, one (b,o) per thread.
// ---------------------------------------------------------------------------
__global__ __launch_bounds__(512) void einsum_kernel(const float* __restrict__ Wr,
                                                     const float* __restrict__ Wi) {
    __shared__ float sWr[64][64];
    __shared__ float sWi[64][64];
    __shared__ float sXr[8][64];
    __shared__ float sXi[8][64];

    const int kh = blockIdx.x;
    const int k = kh >> 3;
    const int h = kh & 7;
    const int tid = threadIdx.x;

    const float4* wr4 = (const float4*)(Wr + (size_t)kh * 4096);
    const float4* wi4 = (const float4*)(Wi + (size_t)kh * 4096);
    float4* sWr4 = (float4*)sWr;
    float4* sWi4 = (float4*)sWi;
#pragma unroll
    for (int e = 0; e < 2; e++) {
        sWr4[tid + e * 512] = wr4[tid + e * 512];
        sWi4[tid + e * 512] = wi4[tid + e * 512];
    }
    {
        const int b = tid >> 6, i = tid & 63;
        float sr = 0.f, si = 0.f;
        const float* p = g_Xpart + (size_t)b * (128 * NC) + (size_t)k * NC + h * 64 + i;
#pragma unroll
        for (int s = 0; s < RSPLIT; s++) {
            sr += p[0];
            si += p[64 * NC];
            p += (size_t)NB * 128 * NC;
        }
        sXr[b][i] = sr;
        sXi[b][i] = si;
    }
    __syncthreads();

    const int o = tid & 63;
    const int bb = tid >> 6;
    const float w = (k == 0 ? 1.0f : 2.0f) / (float)L_LEN;
    float ar = 0.f, ai = 0.f;
#pragma unroll
    for (int i = 0; i < 64; i++) {
        const float xr = sXr[bb][i], xi = sXi[bb][i];
        const float wrv = sWr[i][o], wiv = sWi[i][o];
        ar += xr * wrv - xi * wiv;
        ai += xr * wiv + xi * wrv;
    }
    const size_t pr = (size_t)bb * (128 * NC) + (size_t)k * NC + h * 64 + o;
    const size_t pi = (size_t)bb * (128 * NC) + (size_t)(64 + k) * NC + h * 64 + o;
    __nv_bfloat16 hh, ll;
    split2(ar * w, hh, ll);
    g_Y_h[pr] = hh; g_Y_l[pr] = ll;
    split2(ai * w, hh, ll);
    g_Y_h[pi] = hh; g_Y_l[pi] = ll;
}

// ---------------------------------------------------------------------------
// inputs (metadata order): q, k, v, W_real, W_imag, mask
// ---------------------------------------------------------------------------
extern "C" void kernel_launch(void* const* d_in, const int* in_sizes, int n_in,
                              void* d_out, int out_size) {
    const float* q  = (const float*)d_in[0];
    const float* Wr = (const float*)d_in[3];
    const float* Wi = (const float*)d_in[4];
    float* out = (float*)d_out;

    static bool attr_done = false;
    if (!attr_done) {
        cudaFuncSetAttribute(mma_gemm<0>, cudaFuncAttributeMaxDynamicSharedMemorySize,
                             2 * BUFBYTES);
        cudaFuncSetAttribute(mma_gemm<1>, cudaFuncAttributeMaxDynamicSharedMemorySize,
                             2 * BUFBYTES);
        attr_done = true;
    }

    init_kernel<<<(128 * L_LEN + 255) / 256, 256>>>();
    mma_gemm<0><<<dim3(4, RSPLIT, NB), 256, 2 * BUFBYTES>>>(q, nullptr);
    einsum_kernel<<<KF * NH, 512>>>(Wr, Wi);
    mma_gemm<1><<<dim3(4, L_LEN / 128, NB), 256, 2 * BUFBYTES>>>(nullptr, out);
}

// round 7
// speedup vs baseline: 2.5869x; 1.0180x over previous
#include <cuda_runtime.h>
#include <cuda_bf16.h>

// FourierBlock: y = irfft( pad_K( (rfft(q)[:, :64]) @ (Wr + i Wi) ) )
// Two dense GEMMs on tensor cores (bf16 hi/lo 3-term split, pass-fused) plus
// a small complex-mix kernel. 128x64 CTA tiles -> 2 CTAs/SM.

#define L_LEN 4096
#define NB 8
#define NH 8
#define KF 64
#define NC 512
#define RSPLIT 4

// ---- scratch (all __device__ globals; no allocs) ----
__device__ __align__(16) __nv_bfloat16 g_fb_h[128 * L_LEN];
__device__ __align__(16) __nv_bfloat16 g_fb_l[128 * L_LEN];
__device__ __align__(16) __nv_bfloat16 g_ib_h[L_LEN * 128];
__device__ __align__(16) __nv_bfloat16 g_ib_l[L_LEN * 128];
__device__ __align__(16) __nv_bfloat16 g_Y_h[NB * 128 * NC];
__device__ __align__(16) __nv_bfloat16 g_Y_l[NB * 128 * NC];
__device__ __align__(16) float g_Xpart[RSPLIT * NB * 128 * NC];

__device__ __forceinline__ void split2(float v, __nv_bfloat16& h, __nv_bfloat16& l) {
    h = __float2bfloat16(v);
    l = __float2bfloat16(v - __bfloat162float(h));
}

// ---------------------------------------------------------------------------
// Basis init: 128x4096 twiddles, hi/lo, both layouts.
// ---------------------------------------------------------------------------
__global__ __launch_bounds__(256) void init_kernel() {
    int idx = blockIdx.x * blockDim.x + threadIdx.x;
    if (idx >= 128 * L_LEN) return;
    int r = idx >> 12;
    int l = idx & (L_LEN - 1);
    int k = r & 63;
    int m = (k * l) & (L_LEN - 1);
    float s, c;
    sincospif(2.0f * (float)m / 4096.0f, &s, &c);
    float v = (r < 64) ? c : -s;
    __nv_bfloat16 h, lo;
    split2(v, h, lo);
    g_fb_h[idx] = h;          g_fb_l[idx] = lo;
    g_ib_h[l * 128 + r] = h;  g_ib_l[l * 128 + r] = lo;
}

// ---------------------------------------------------------------------------
// Pass-fused MMA GEMM, 128x64 CTA tile, 8 warps (4x2, each 32x32), m16n8k16.
// Per k-chunk: stage Ah, Al, Bh, Bl; issue Ah*Bh + Ah*Bl + Al*Bh.
// MODE 0: A = fbasis(128x4096), B = fp32 q_b (converted in-flight),
//         split-K over l -> g_Xpart partials.
// MODE 1: A = ibasis(4096x128), B = Y_b (bf16 hi/lo via cp.async) -> out.
// ---------------------------------------------------------------------------
#define TKC 64
#define ASTR 72                      // bf16 elems per smem row (64 + 8 pad)
#define BSTR 72                      // (64 + 8 pad)
#define ATILE (128 * ASTR * 2)       // 18432 bytes
#define BTILE (TKC * BSTR * 2)       // 9216 bytes
#define BUFBYTES (2 * ATILE + 2 * BTILE)  // 55296

#define CP_ASYNC16(dst_u32, src) \
    asm volatile("cp.async.cg.shared.global [%0], [%1], 16;\n" :: "r"(dst_u32), "l"(src))
#define CP_COMMIT() asm volatile("cp.async.commit_group;\n" ::)
#define CP_WAIT1() asm volatile("cp.async.wait_group 1;\n" ::)
#define CP_WAIT0() asm volatile("cp.async.wait_group 0;\n" ::)

template <int MODE>
__global__ __launch_bounds__(256, 2) void mma_gemm(const float* __restrict__ Bf32,
                                                   float* __restrict__ Cext) {
    constexpr int KD = (MODE == 0) ? L_LEN : 128;
    constexpr int NCHUNK = (MODE == 0) ? (L_LEN / RSPLIT) / TKC : 128 / TKC; // 16 : 2

    const int b = blockIdx.z;
    const int col0 = blockIdx.x * 64;
    int row0, kbeg;
    const __nv_bfloat16 *Ah, *Al, *Bh = nullptr, *Bl = nullptr;
    const float* Bq = nullptr;
    float* Cb;
    if (MODE == 0) {
        row0 = 0;
        kbeg = blockIdx.y * (L_LEN / RSPLIT);
        Ah = g_fb_h; Al = g_fb_l;
        Bq = Bf32 + (size_t)b * (L_LEN * NC);
        Cb = g_Xpart + ((size_t)blockIdx.y * NB + b) * (128 * NC);
    } else {
        row0 = blockIdx.y * 128;
        kbeg = 0;
        Ah = g_ib_h; Al = g_ib_l;
        Bh = g_Y_h + (size_t)b * (128 * NC);
        Bl = g_Y_l + (size_t)b * (128 * NC);
        Cb = Cext + (size_t)b * (L_LEN * NC);
    }

    extern __shared__ __align__(16) char smem[];
    const unsigned smem_u32 = (unsigned)__cvta_generic_to_shared(smem);
    const int tid = threadIdx.x;
    const int lane = tid & 31, wid = tid >> 5;
    const int wm = wid & 3, wn = wid >> 2;   // 4 x 2 warps, each 32(M) x 32(N)

    float acc[2][4][4];
#pragma unroll
    for (int mi = 0; mi < 2; mi++)
#pragma unroll
        for (int ni = 0; ni < 4; ni++)
#pragma unroll
            for (int r = 0; r < 4; r++) acc[mi][ni][r] = 0.0f;

    // A tiles via cp.async (both modes); MODE 1 also stages B via cp.async.
    auto prefetch = [&](int ch) {
        const int k0 = kbeg + ch * TKC;
        const unsigned base = smem_u32 + (ch & 1) * BUFBYTES;
#pragma unroll
        for (int i = 0; i < 4; i++) {                 // A tiles: 128 x 64 each
            int idx = tid + i * 256;
            int r = idx >> 3, s8 = idx & 7;
            const size_t off = (size_t)(row0 + r) * KD + k0 + s8 * 8;
            CP_ASYNC16(base + r * (ASTR * 2) + s8 * 16, Ah + off);
            CP_ASYNC16(base + ATILE + r * (ASTR * 2) + s8 * 16, Al + off);
        }
        if (MODE == 1) {
#pragma unroll
            for (int i = 0; i < 2; i++) {             // B tiles: 64 x 64 each
                int idx = tid + i * 256;
                int r = idx >> 3, s8 = idx & 7;
                const size_t off = (size_t)(k0 + r) * NC + col0 + s8 * 8;
                CP_ASYNC16(base + 2 * ATILE + r * (BSTR * 2) + s8 * 16, Bh + off);
                CP_ASYNC16(base + 2 * ATILE + BTILE + r * (BSTR * 2) + s8 * 16, Bl + off);
            }
        }
        CP_COMMIT();
    };

    // MODE 0: B fp32 register staging + in-flight bf16 split.
    float4 breg[4];
    auto ldgB = [&](int ch) {
        const int k0 = kbeg + ch * TKC;
#pragma unroll
        for (int i = 0; i < 4; i++) {
            int idx = tid + i * 256;
            int r = idx >> 4, c4 = idx & 15;          // 64 rows x 16 float4 segs
            breg[i] = *(const float4*)(Bq + (size_t)(k0 + r) * NC + col0 + c4 * 4);
        }
    };
    auto stsB = [&](int ch) {
        char* base = smem + (ch & 1) * BUFBYTES + 2 * ATILE;
#pragma unroll
        for (int i = 0; i < 4; i++) {
            int idx = tid + i * 256;
            int r = idx >> 4, c4 = idx & 15;
            __nv_bfloat16 h0, l0, h1, l1, h2, l2, h3, l3;
            split2(breg[i].x, h0, l0); split2(breg[i].y, h1, l1);
            split2(breg[i].z, h2, l2); split2(breg[i].w, h3, l3);
            const int off = r * (BSTR * 2) + c4 * 8;
            __nv_bfloat162* ph = (__nv_bfloat162*)(base + off);
            __nv_bfloat162* pl = (__nv_bfloat162*)(base + BTILE + off);
            ph[0] = __nv_bfloat162(h0, h1); ph[1] = __nv_bfloat162(h2, h3);
            pl[0] = __nv_bfloat162(l0, l1); pl[1] = __nv_bfloat162(l2, l3);
        }
    };

    if (MODE == 0) ldgB(0);
    prefetch(0);

    for (int it = 0; it < NCHUNK; it++) {
        if (MODE == 0) stsB(it);
        if (it + 1 < NCHUNK) {
            if (MODE == 0) ldgB(it + 1);
            prefetch(it + 1);
            CP_WAIT1();
        } else {
            CP_WAIT0();
        }
        __syncthreads();

        const unsigned base = smem_u32 + (it & 1) * BUFBYTES;
#pragma unroll
        for (int kstep = 0; kstep < TKC / 16; kstep++) {
            unsigned fah[2][4], fal[2][4], fbh[4][2], fbl[4][2];
#pragma unroll
            for (int mi = 0; mi < 2; mi++) {
                unsigned addr = base +
                    (unsigned)((wm * 32 + mi * 16 + (lane & 15)) * (ASTR * 2) +
                               kstep * 32 + (lane >> 4) * 16);
                asm volatile("ldmatrix.sync.aligned.m8n8.x4.shared.b16 {%0,%1,%2,%3}, [%4];"
                             : "=r"(fah[mi][0]), "=r"(fah[mi][1]), "=r"(fah[mi][2]), "=r"(fah[mi][3])
                             : "r"(addr));
                asm volatile("ldmatrix.sync.aligned.m8n8.x4.shared.b16 {%0,%1,%2,%3}, [%4];"
                             : "=r"(fal[mi][0]), "=r"(fal[mi][1]), "=r"(fal[mi][2]), "=r"(fal[mi][3])
                             : "r"(addr + ATILE));
            }
#pragma unroll
            for (int ni = 0; ni < 4; ni++) {
                unsigned addr = base + 2 * ATILE +
                    (unsigned)((kstep * 16 + (lane & 15)) * (BSTR * 2) +
                               (wn * 32 + ni * 8) * 2);
                asm volatile("ldmatrix.sync.aligned.m8n8.x2.trans.shared.b16 {%0,%1}, [%2];"
                             : "=r"(fbh[ni][0]), "=r"(fbh[ni][1]) : "r"(addr));
                asm volatile("ldmatrix.sync.aligned.m8n8.x2.trans.shared.b16 {%0,%1}, [%2];"
                             : "=r"(fbl[ni][0]), "=r"(fbl[ni][1]) : "r"(addr + BTILE));
            }
#pragma unroll
            for (int mi = 0; mi < 2; mi++)
#pragma unroll
                for (int ni = 0; ni < 4; ni++) {
#define MMA_BF16(A0,A1,A2,A3,B0,B1)                                            \
    asm volatile("mma.sync.aligned.m16n8k16.row.col.f32.bf16.bf16.f32 "        \
                 "{%0,%1,%2,%3}, {%4,%5,%6,%7}, {%8,%9}, {%0,%1,%2,%3};"       \
                 : "+f"(acc[mi][ni][0]), "+f"(acc[mi][ni][1]),                 \
                   "+f"(acc[mi][ni][2]), "+f"(acc[mi][ni][3])                  \
                 : "r"(A0), "r"(A1), "r"(A2), "r"(A3), "r"(B0), "r"(B1))
                    MMA_BF16(fah[mi][0], fah[mi][1], fah[mi][2], fah[mi][3],
                             fbh[ni][0], fbh[ni][1]);
                    MMA_BF16(fah[mi][0], fah[mi][1], fah[mi][2], fah[mi][3],
                             fbl[ni][0], fbl[ni][1]);
                    MMA_BF16(fal[mi][0], fal[mi][1], fal[mi][2], fal[mi][3],
                             fbh[ni][0], fbh[ni][1]);
#undef MMA_BF16
                }
        }
        __syncthreads();
    }

    const int g = lane >> 2, tig = lane & 3;
#pragma unroll
    for (int mi = 0; mi < 2; mi++)
#pragma unroll
        for (int ni = 0; ni < 4; ni++) {
            int r = row0 + wm * 32 + mi * 16 + g;
            int c = col0 + wn * 32 + ni * 8 + tig * 2;
            *(float2*)&Cb[(size_t)r * NC + c] = make_float2(acc[mi][ni][0], acc[mi][ni][1]);
            *(float2*)&Cb[(size_t)(r + 8) * NC + c] = make_float2(acc[mi][ni][2], acc[mi][ni][3]);
        }
}

// ---------------------------------------------------------------------------
// Split-K reduce + per-(k,h) complex mix; 512 threads, one (b,o) per thread.
// ---------------------------------------------------------------------------
__global__ __launch_bounds__(512) void einsum_kernel(const float* __restrict__ Wr,
                                                     const float* __restrict__ Wi) {
    __shared__ float sWr[64][64];
    __shared__ float sWi[64][64];
    __shared__ float sXr[8][64];
    __shared__ float sXi[8][64];

    const int kh = blockIdx.x;
    const int k = kh >> 3;
    const int h = kh & 7;
    const int tid = threadIdx.x;

    const float4* wr4 = (const float4*)(Wr + (size_t)kh * 4096);
    const float4* wi4 = (const float4*)(Wi + (size_t)kh * 4096);
    float4* sWr4 = (float4*)sWr;
    float4* sWi4 = (float4*)sWi;
#pragma unroll
    for (int e = 0; e < 2; e++) {
        sWr4[tid + e * 512] = wr4[tid + e * 512];
        sWi4[tid + e * 512] = wi4[tid + e * 512];
    }
    {
        const int b = tid >> 6, i = tid & 63;
        float sr = 0.f, si = 0.f;
        const float* p = g_Xpart + (size_t)b * (128 * NC) + (size_t)k * NC + h * 64 + i;
#pragma unroll
        for (int s = 0; s < RSPLIT; s++) {
            sr += p[0];
            si += p[64 * NC];
            p += (size_t)NB * 128 * NC;
        }
        sXr[b][i] = sr;
        sXi[b][i] = si;
    }
    __syncthreads();

    const int o = tid & 63;
    const int bb = tid >> 6;
    const float w = (k == 0 ? 1.0f : 2.0f) / (float)L_LEN;
    float ar = 0.f, ai = 0.f;
#pragma unroll
    for (int i = 0; i < 64; i++) {
        const float xr = sXr[bb][i], xi = sXi[bb][i];
        const float wrv = sWr[i][o], wiv = sWi[i][o];
        ar += xr * wrv - xi * wiv;
        ai += xr * wiv + xi * wrv;
    }
    const size_t pr = (size_t)bb * (128 * NC) + (size_t)k * NC + h * 64 + o;
    const size_t pi = (size_t)bb * (128 * NC) + (size_t)(64 + k) * NC + h * 64 + o;
    __nv_bfloat16 hh, ll;
    split2(ar * w, hh, ll);
    g_Y_h[pr] = hh; g_Y_l[pr] = ll;
    split2(ai * w, hh, ll);
    g_Y_h[pi] = hh; g_Y_l[pi] = ll;
}

// ---------------------------------------------------------------------------
// inputs (metadata order): q, k, v, W_real, W_imag, mask
// ---------------------------------------------------------------------------
extern "C" void kernel_launch(void* const* d_in, const int* in_sizes, int n_in,
                              void* d_out, int out_size) {
    const float* q  = (const float*)d_in[0];
    const float* Wr = (const float*)d_in[3];
    const float* Wi = (const float*)d_in[4];
    float* out = (float*)d_out;

    static bool attr_done = false;
    if (!attr_done) {
        cudaFuncSetAttribute(mma_gemm<0>, cudaFuncAttributeMaxDynamicSharedMemorySize,
                             2 * BUFBYTES);
        cudaFuncSetAttribute(mma_gemm<1>, cudaFuncAttributeMaxDynamicSharedMemorySize,
                             2 * BUFBYTES);
        attr_done = true;
    }

    init_kernel<<<(128 * L_LEN + 255) / 256, 256>>>();
    mma_gemm<0><<<dim3(8, RSPLIT, NB), 256, 2 * BUFBYTES>>>(q, nullptr);
    einsum_kernel<<<KF * NH, 512>>>(Wr, Wi);
    mma_gemm<1><<<dim3(8, L_LEN / 128, NB), 256, 2 * BUFBYTES>>>(nullptr, out);
}

// round 9
// speedup vs baseline: 2.6165x; 1.0114x over previous
#include <cuda_runtime.h>
#include <cuda_bf16.h>

// FourierBlock: y = irfft( pad_K( (rfft(q)[:, :64]) @ (Wr + i Wi) ) )
// Forward GEMM: pass-fused bf16 hi/lo MMA with in-flight fp32->bf16 split.
// Inverse GEMM: B-resident (Y in smem once), streams ibasis over 2 M-blocks.

#define L_LEN 4096
#define NB 8
#define NH 8
#define KF 64
#define NC 512
#define RSPLIT 4

// ---- scratch (all __device__ globals; no allocs) ----
__device__ __align__(16) __nv_bfloat16 g_fb_h[128 * L_LEN];
__device__ __align__(16) __nv_bfloat16 g_fb_l[128 * L_LEN];
__device__ __align__(16) __nv_bfloat16 g_ib_h[L_LEN * 128];
__device__ __align__(16) __nv_bfloat16 g_ib_l[L_LEN * 128];
__device__ __align__(16) __nv_bfloat16 g_Y_h[NB * 128 * NC];
__device__ __align__(16) __nv_bfloat16 g_Y_l[NB * 128 * NC];
__device__ __align__(16) float g_Xpart[RSPLIT * NB * 128 * NC];

__device__ __forceinline__ void split2(float v, __nv_bfloat16& h, __nv_bfloat16& l) {
    h = __float2bfloat16(v);
    l = __float2bfloat16(v - __bfloat162float(h));
}

// ---------------------------------------------------------------------------
// Basis init: 128x4096 twiddles, hi/lo, both layouts.
// ---------------------------------------------------------------------------
__global__ __launch_bounds__(256) void init_kernel() {
    int idx = blockIdx.x * blockDim.x + threadIdx.x;
    if (idx >= 128 * L_LEN) return;
    int r = idx >> 12;
    int l = idx & (L_LEN - 1);
    int k = r & 63;
    int m = (k * l) & (L_LEN - 1);
    float s, c;
    sincospif(2.0f * (float)m / 4096.0f, &s, &c);
    float v = (r < 64) ? c : -s;
    __nv_bfloat16 h, lo;
    split2(v, h, lo);
    g_fb_h[idx] = h;          g_fb_l[idx] = lo;
    g_ib_h[l * 128 + r] = h;  g_ib_l[l * 128 + r] = lo;
}

#define CP_ASYNC16(dst_u32, src) \
    asm volatile("cp.async.cg.shared.global [%0], [%1], 16;\n" :: "r"(dst_u32), "l"(src))
#define CP_COMMIT() asm volatile("cp.async.commit_group;\n" ::)
#define CP_WAIT1() asm volatile("cp.async.wait_group 1;\n" ::)
#define CP_WAIT0() asm volatile("cp.async.wait_group 0;\n" ::)

#define MMA_BF16(ACC, A0, A1, A2, A3, B0, B1)                                  \
    asm volatile("mma.sync.aligned.m16n8k16.row.col.f32.bf16.bf16.f32 "        \
                 "{%0,%1,%2,%3}, {%4,%5,%6,%7}, {%8,%9}, {%0,%1,%2,%3};"       \
                 : "+f"(ACC[0]), "+f"(ACC[1]), "+f"(ACC[2]), "+f"(ACC[3])      \
                 : "r"(A0), "r"(A1), "r"(A2), "r"(A3), "r"(B0), "r"(B1))

// ---------------------------------------------------------------------------
// Forward pass-fused MMA GEMM (round-7 winner, unchanged).
// 128x64 CTA tile, 8 warps (4x2, each 32x32). A = fbasis, B = fp32 q
// (converted in-flight), split-K over l -> g_Xpart partials.
// ---------------------------------------------------------------------------
#define TKC 64
#define ASTR 72
#define BSTR 72
#define ATILE (128 * ASTR * 2)       // 18432
#define BTILE (TKC * BSTR * 2)       // 9216
#define BUFBYTES (2 * ATILE + 2 * BTILE)  // 55296

__global__ __launch_bounds__(256, 2) void fwd_gemm(const float* __restrict__ Bf32) {
    constexpr int KD = L_LEN;
    constexpr int NCHUNK = (L_LEN / RSPLIT) / TKC;   // 16

    const int b = blockIdx.z;
    const int col0 = blockIdx.x * 64;
    const int kbeg = blockIdx.y * (L_LEN / RSPLIT);
    const __nv_bfloat16* Ah = g_fb_h;
    const __nv_bfloat16* Al = g_fb_l;
    const float* Bq = Bf32 + (size_t)b * (L_LEN * NC);
    float* Cb = g_Xpart + ((size_t)blockIdx.y * NB + b) * (128 * NC);

    extern __shared__ __align__(16) char smem[];
    const unsigned smem_u32 = (unsigned)__cvta_generic_to_shared(smem);
    const int tid = threadIdx.x;
    const int lane = tid & 31, wid = tid >> 5;
    const int wm = wid & 3, wn = wid >> 2;

    float acc[2][4][4];
#pragma unroll
    for (int mi = 0; mi < 2; mi++)
#pragma unroll
        for (int ni = 0; ni < 4; ni++)
#pragma unroll
            for (int r = 0; r < 4; r++) acc[mi][ni][r] = 0.0f;

    auto prefetchA = [&](int ch) {
        const int k0 = kbeg + ch * TKC;
        const unsigned base = smem_u32 + (ch & 1) * BUFBYTES;
#pragma unroll
        for (int i = 0; i < 4; i++) {
            int idx = tid + i * 256;
            int r = idx >> 3, s8 = idx & 7;
            const size_t off = (size_t)r * KD + k0 + s8 * 8;
            CP_ASYNC16(base + r * (ASTR * 2) + s8 * 16, Ah + off);
            CP_ASYNC16(base + ATILE + r * (ASTR * 2) + s8 * 16, Al + off);
        }
        CP_COMMIT();
    };

    float4 breg[4];
    auto ldgB = [&](int ch) {
        const int k0 = kbeg + ch * TKC;
#pragma unroll
        for (int i = 0; i < 4; i++) {
            int idx = tid + i * 256;
            int r = idx >> 4, c4 = idx & 15;
            breg[i] = *(const float4*)(Bq + (size_t)(k0 + r) * NC + col0 + c4 * 4);
        }
    };
    auto stsB = [&](int ch) {
        char* base = smem + (ch & 1) * BUFBYTES + 2 * ATILE;
#pragma unroll
        for (int i = 0; i < 4; i++) {
            int idx = tid + i * 256;
            int r = idx >> 4, c4 = idx & 15;
            __nv_bfloat16 h0, l0, h1, l1, h2, l2, h3, l3;
            split2(breg[i].x, h0, l0); split2(breg[i].y, h1, l1);
            split2(breg[i].z, h2, l2); split2(breg[i].w, h3, l3);
            const int off = r * (BSTR * 2) + c4 * 8;
            __nv_bfloat162* ph = (__nv_bfloat162*)(base + off);
            __nv_bfloat162* pl = (__nv_bfloat162*)(base + BTILE + off);
            ph[0] = __nv_bfloat162(h0, h1); ph[1] = __nv_bfloat162(h2, h3);
            pl[0] = __nv_bfloat162(l0, l1); pl[1] = __nv_bfloat162(l2, l3);
        }
    };

    ldgB(0);
    prefetchA(0);

    for (int it = 0; it < NCHUNK; it++) {
        stsB(it);
        if (it + 1 < NCHUNK) {
            ldgB(it + 1);
            prefetchA(it + 1);
            CP_WAIT1();
        } else {
            CP_WAIT0();
        }
        __syncthreads();

        const unsigned base = smem_u32 + (it & 1) * BUFBYTES;
#pragma unroll
        for (int kstep = 0; kstep < TKC / 16; kstep++) {
            unsigned fah[2][4], fal[2][4], fbh[4][2], fbl[4][2];
#pragma unroll
            for (int mi = 0; mi < 2; mi++) {
                unsigned addr = base +
                    (unsigned)((wm * 32 + mi * 16 + (lane & 15)) * (ASTR * 2) +
                               kstep * 32 + (lane >> 4) * 16);
                asm volatile("ldmatrix.sync.aligned.m8n8.x4.shared.b16 {%0,%1,%2,%3}, [%4];"
                             : "=r"(fah[mi][0]), "=r"(fah[mi][1]), "=r"(fah[mi][2]), "=r"(fah[mi][3])
                             : "r"(addr));
                asm volatile("ldmatrix.sync.aligned.m8n8.x4.shared.b16 {%0,%1,%2,%3}, [%4];"
                             : "=r"(fal[mi][0]), "=r"(fal[mi][1]), "=r"(fal[mi][2]), "=r"(fal[mi][3])
                             : "r"(addr + ATILE));
            }
#pragma unroll
            for (int ni = 0; ni < 4; ni++) {
                unsigned addr = base + 2 * ATILE +
                    (unsigned)((kstep * 16 + (lane & 15)) * (BSTR * 2) +
                               (wn * 32 + ni * 8) * 2);
                asm volatile("ldmatrix.sync.aligned.m8n8.x2.trans.shared.b16 {%0,%1}, [%2];"
                             : "=r"(fbh[ni][0]), "=r"(fbh[ni][1]) : "r"(addr));
                asm volatile("ldmatrix.sync.aligned.m8n8.x2.trans.shared.b16 {%0,%1}, [%2];"
                             : "=r"(fbl[ni][0]), "=r"(fbl[ni][1]) : "r"(addr + BTILE));
            }
#pragma unroll
            for (int mi = 0; mi < 2; mi++)
#pragma unroll
                for (int ni = 0; ni < 4; ni++) {
                    MMA_BF16(acc[mi][ni], fah[mi][0], fah[mi][1], fah[mi][2], fah[mi][3],
                             fbh[ni][0], fbh[ni][1]);
                    MMA_BF16(acc[mi][ni], fah[mi][0], fah[mi][1], fah[mi][2], fah[mi][3],
                             fbl[ni][0], fbl[ni][1]);
                    MMA_BF16(acc[mi][ni], fal[mi][0], fal[mi][1], fal[mi][2], fal[mi][3],
                             fbh[ni][0], fbh[ni][1]);
                }
        }
        __syncthreads();
    }

    const int g = lane >> 2, tig = lane & 3;
#pragma unroll
    for (int mi = 0; mi < 2; mi++)
#pragma unroll
        for (int ni = 0; ni < 4; ni++) {
            int r = wm * 32 + mi * 16 + g;
            int c = col0 + wn * 32 + ni * 8 + tig * 2;
            *(float2*)&Cb[(size_t)r * NC + c] = make_float2(acc[mi][ni][0], acc[mi][ni][1]);
            *(float2*)&Cb[(size_t)(r + 8) * NC + c] = make_float2(acc[mi][ni][2], acc[mi][ni][3]);
        }
}

// ---------------------------------------------------------------------------
// Inverse GEMM, B-resident: Y (128 x 64 hi/lo = 32 KB) loaded to smem ONCE;
// A (ibasis) streamed over 2 M-blocks x 2 k-chunks (4-deep pipeline).
// CTA: 256 l-rows x 64 cols. 8 warps 4x2, each 32x32.
// ---------------------------------------------------------------------------
#define IBSTR 72
#define IB_MAT (128 * IBSTR * 2)          // 18432 bytes, one 128x64 bf16 matrix
#define IV_AOFF (2 * IB_MAT)              // B: [Yh][Yl]
#define IV_ABUF (2 * IB_MAT)              // per buffer: [Ah][Al]
#define IV_SMEM (IV_AOFF + 2 * IV_ABUF)   // 110592

__global__ __launch_bounds__(256, 2) void inv_gemm(float* __restrict__ Cext) {
    const int b = blockIdx.z;
    const int col0 = blockIdx.x * 64;
    const int m0 = blockIdx.y * 256;
    const __nv_bfloat16* Bh = g_Y_h + (size_t)b * (128 * NC);
    const __nv_bfloat16* Bl = g_Y_l + (size_t)b * (128 * NC);
    float* Cb = Cext + (size_t)b * (L_LEN * NC);

    extern __shared__ __align__(16) char smem[];
    const unsigned su = (unsigned)__cvta_generic_to_shared(smem);
    const int tid = threadIdx.x;
    const int lane = tid & 31, wid = tid >> 5;
    const int wm = wid & 3, wn = wid >> 2;

    // Stage B (Y hi/lo, all 128 k-rows) — issued now, grouped with A0 commit.
#pragma unroll
    for (int i = 0; i < 4; i++) {
        int idx = tid + i * 256;
        int r = idx >> 3, s8 = idx & 7;
        const size_t off = (size_t)r * NC + col0 + s8 * 8;
        CP_ASYNC16(su + r * (IBSTR * 2) + s8 * 16, Bh + off);
        CP_ASYNC16(su + IB_MAT + r * (IBSTR * 2) + s8 * 16, Bl + off);
    }

    auto prefA = [&](int it) {   // it = mb*2 + chunk
        const int mb = it >> 1, c = it & 1;
        const unsigned base = su + IV_AOFF + (it & 1) * IV_ABUF;
#pragma unroll
        for (int i = 0; i < 4; i++) {
            int idx = tid + i * 256;
            int r = idx >> 3, s8 = idx & 7;
            const size_t off = (size_t)(m0 + mb * 128 + r) * 128 + c * 64 + s8 * 8;
            CP_ASYNC16(base + r * (IBSTR * 2) + s8 * 16, g_ib_h + off);
            CP_ASYNC16(base + IB_MAT + r * (IBSTR * 2) + s8 * 16, g_ib_l + off);
        }
        CP_COMMIT();
    };

    prefA(0);   // group 0 = B + A0

    float acc[2][4][4];
#pragma unroll
    for (int mi = 0; mi < 2; mi++)
#pragma unroll
        for (int ni = 0; ni < 4; ni++)
#pragma unroll
            for (int r = 0; r < 4; r++) acc[mi][ni][r] = 0.0f;

    const int g = lane >> 2, tig = lane & 3;

    for (int it = 0; it < 4; it++) {
        if (it + 1 < 4) { prefA(it + 1); CP_WAIT1(); }
        else { CP_WAIT0(); }
        __syncthreads();

        const int c = it & 1;
        const unsigned abase = su + IV_AOFF + (it & 1) * IV_ABUF;
#pragma unroll
        for (int kstep = 0; kstep < 4; kstep++) {
            unsigned fah[2][4], fal[2][4], fbh[4][2], fbl[4][2];
#pragma unroll
            for (int mi = 0; mi < 2; mi++) {
                unsigned addr = abase +
                    (unsigned)((wm * 32 + mi * 16 + (lane & 15)) * (IBSTR * 2) +
                               kstep * 32 + (lane >> 4) * 16);
                asm volatile("ldmatrix.sync.aligned.m8n8.x4.shared.b16 {%0,%1,%2,%3}, [%4];"
                             : "=r"(fah[mi][0]), "=r"(fah[mi][1]), "=r"(fah[mi][2]), "=r"(fah[mi][3])
                             : "r"(addr));
                asm volatile("ldmatrix.sync.aligned.m8n8.x4.shared.b16 {%0,%1,%2,%3}, [%4];"
                             : "=r"(fal[mi][0]), "=r"(fal[mi][1]), "=r"(fal[mi][2]), "=r"(fal[mi][3])
                             : "r"(addr + IB_MAT));
            }
#pragma unroll
            for (int ni = 0; ni < 4; ni++) {
                unsigned addr = su +
                    (unsigned)((c * 64 + kstep * 16 + (lane & 15)) * (IBSTR * 2) +
                               (wn * 32 + ni * 8) * 2);
                asm volatile("ldmatrix.sync.aligned.m8n8.x2.trans.shared.b16 {%0,%1}, [%2];"
                             : "=r"(fbh[ni][0]), "=r"(fbh[ni][1]) : "r"(addr));
                asm volatile("ldmatrix.sync.aligned.m8n8.x2.trans.shared.b16 {%0,%1}, [%2];"
                             : "=r"(fbl[ni][0]), "=r"(fbl[ni][1]) : "r"(addr + IB_MAT));
            }
#pragma unroll
            for (int mi = 0; mi < 2; mi++)
#pragma unroll
                for (int ni = 0; ni < 4; ni++) {
                    MMA_BF16(acc[mi][ni], fah[mi][0], fah[mi][1], fah[mi][2], fah[mi][3],
                             fbh[ni][0], fbh[ni][1]);
                    MMA_BF16(acc[mi][ni], fah[mi][0], fah[mi][1], fah[mi][2], fah[mi][3],
                             fbl[ni][0], fbl[ni][1]);
                    MMA_BF16(acc[mi][ni], fal[mi][0], fal[mi][1], fal[mi][2], fal[mi][3],
                             fbh[ni][0], fbh[ni][1]);
                }
        }

        if (c == 1) {   // m-block complete: write out, reset accumulators
            const int mb = it >> 1;
#pragma unroll
            for (int mi = 0; mi < 2; mi++)
#pragma unroll
                for (int ni = 0; ni < 4; ni++) {
                    int r = m0 + mb * 128 + wm * 32 + mi * 16 + g;
                    int cc = col0 + wn * 32 + ni * 8 + tig * 2;
                    *(float2*)&Cb[(size_t)r * NC + cc] =
                        make_float2(acc[mi][ni][0], acc[mi][ni][1]);
                    *(float2*)&Cb[(size_t)(r + 8) * NC + cc] =
                        make_float2(acc[mi][ni][2], acc[mi][ni][3]);
#pragma unroll
                    for (int q = 0; q < 4; q++) acc[mi][ni][q] = 0.0f;
                }
        }
        __syncthreads();
    }
}

// ---------------------------------------------------------------------------
// Split-K reduce + per-(k,h) complex mix; 512 threads, one (b,o) per thread.
// ---------------------------------------------------------------------------
__global__ __launch_bounds__(512) void einsum_kernel(const float* __restrict__ Wr,
                                                     const float* __restrict__ Wi) {
    __shared__ float sWr[64][64];
    __shared__ float sWi[64][64];
    __shared__ float sXr[8][64];
    __shared__ float sXi[8][64];

    const int kh = blockIdx.x;
    const int k = kh >> 3;
    const int h = kh & 7;
    const int tid = threadIdx.x;

    const float4* wr4 = (const float4*)(Wr + (size_t)kh * 4096);
    const float4* wi4 = (const float4*)(Wi + (size_t)kh * 4096);
    float4* sWr4 = (float4*)sWr;
    float4* sWi4 = (float4*)sWi;
#pragma unroll
    for (int e = 0; e < 2; e++) {
        sWr4[tid + e * 512] = wr4[tid + e * 512];
        sWi4[tid + e * 512] = wi4[tid + e * 512];
    }
    {
        const int b = tid >> 6, i = tid & 63;
        float sr = 0.f, si = 0.f;
        const float* p = g_Xpart + (size_t)b * (128 * NC) + (size_t)k * NC + h * 64 + i;
#pragma unroll
        for (int s = 0; s < RSPLIT; s++) {
            sr += p[0];
            si += p[64 * NC];
            p += (size_t)NB * 128 * NC;
        }
        sXr[b][i] = sr;
        sXi[b][i] = si;
    }
    __syncthreads();

    const int o = tid & 63;
    const int bb = tid >> 6;
    const float w = (k == 0 ? 1.0f : 2.0f) / (float)L_LEN;
    float ar = 0.f, ai = 0.f;
#pragma unroll
    for (int i = 0; i < 64; i++) {
        const float xr = sXr[bb][i], xi = sXi[bb][i];
        const float wrv = sWr[i][o], wiv = sWi[i][o];
        ar += xr * wrv - xi * wiv;
        ai += xr * wiv + xi * wrv;
    }
    const size_t pr = (size_t)bb * (128 * NC) + (size_t)k * NC + h * 64 + o;
    const size_t pi = (size_t)bb * (128 * NC) + (size_t)(64 + k) * NC + h * 64 + o;
    __nv_bfloat16 hh, ll;
    split2(ar * w, hh, ll);
    g_Y_h[pr] = hh; g_Y_l[pr] = ll;
    split2(ai * w, hh, ll);
    g_Y_h[pi] = hh; g_Y_l[pi] = ll;
}

// ---------------------------------------------------------------------------
// inputs (metadata order): q, k, v, W_real, W_imag, mask
// ---------------------------------------------------------------------------
extern "C" void kernel_launch(void* const* d_in, const int* in_sizes, int n_in,
                              void* d_out, int out_size) {
    const float* q  = (const float*)d_in[0];
    const float* Wr = (const float*)d_in[3];
    const float* Wi = (const float*)d_in[4];
    float* out = (float*)d_out;

    static bool attr_done = false;
    if (!attr_done) {
        cudaFuncSetAttribute(fwd_gemm, cudaFuncAttributeMaxDynamicSharedMemorySize,
                             2 * BUFBYTES);
        cudaFuncSetAttribute(inv_gemm, cudaFuncAttributeMaxDynamicSharedMemorySize,
                             IV_SMEM);
        attr_done = true;
    }

    init_kernel<<<(128 * L_LEN + 255) / 256, 256>>>();
    fwd_gemm<<<dim3(8, RSPLIT, NB), 256, 2 * BUFBYTES>>>(q);
    einsum_kernel<<<KF * NH, 512>>>(Wr, Wi);
    inv_gemm<<<dim3(8, L_LEN / 256, NB), 256, IV_SMEM>>>(out);
}

// round 10
// speedup vs baseline: 2.7913x; 1.0668x over previous
#include <cuda_runtime.h>
#include <cuda_bf16.h>

// FourierBlock: y = irfft( pad_K( (rfft(q)[:, :64]) @ (Wr + i Wi) ) )
// Parity-folded: F[k, l+2048] = (-1)^k F[k, l] halves K of both GEMMs.
// Basis rows/cols permuted: cc = (k&1)*64 + (k>>1), imag at cc+32.
// bf16 hi/lo 3-term split on tensor cores throughout.

#define L_LEN 4096
#define LH 2048
#define NB 8
#define NH 8
#define KF 64
#define NC 512
#define RSPLIT 4

// ---- scratch (all __device__ globals; no allocs) ----
__device__ __align__(16) __nv_bfloat16 g_fb_h[128 * LH];   // [perm_row][l<2048]
__device__ __align__(16) __nv_bfloat16 g_fb_l[128 * LH];
__device__ __align__(16) __nv_bfloat16 g_ib_h[LH * 128];   // [l<2048][perm_col]
__device__ __align__(16) __nv_bfloat16 g_ib_l[LH * 128];
__device__ __align__(16) __nv_bfloat16 g_Y_h[NB * 128 * NC];
__device__ __align__(16) __nv_bfloat16 g_Y_l[NB * 128 * NC];
__device__ __align__(16) float g_Xpart[RSPLIT * NB * 128 * NC];

__device__ __forceinline__ void split2(float v, __nv_bfloat16& h, __nv_bfloat16& l) {
    h = __float2bfloat16(v);
    l = __float2bfloat16(v - __bfloat162float(h));
}

// ---------------------------------------------------------------------------
// Basis init, parity-permuted, half length.
// perm row r: p = r>>6, w = r&63, sinrow = (w>=32), j = w&31, k = 2*j + p.
// value = sinrow ? -sin(2*pi*k*l/4096) : cos(2*pi*k*l/4096),  l in [0,2048).
// ---------------------------------------------------------------------------
__global__ __launch_bounds__(256) void init_kernel() {
    int idx = blockIdx.x * blockDim.x + threadIdx.x;
    if (idx >= 128 * LH) return;
    int r = idx >> 11;
    int l = idx & (LH - 1);
    int p = r >> 6;
    int w = r & 63;
    int j = w & 31;
    int k = 2 * j + p;
    int m = (k * l) & (L_LEN - 1);
    float s, c;
    sincospif(2.0f * (float)m / 4096.0f, &s, &c);
    float v = (w < 32) ? c : -s;
    __nv_bfloat16 h, lo;
    split2(v, h, lo);
    g_fb_h[r * LH + l] = h;   g_fb_l[r * LH + l] = lo;
    g_ib_h[l * 128 + r] = h;  g_ib_l[l * 128 + r] = lo;
}

#define CP_ASYNC16(dst_u32, src) \
    asm volatile("cp.async.cg.shared.global [%0], [%1], 16;\n" :: "r"(dst_u32), "l"(src))
#define CP_COMMIT() asm volatile("cp.async.commit_group;\n" ::)
#define CP_WAIT1() asm volatile("cp.async.wait_group 1;\n" ::)
#define CP_WAIT0() asm volatile("cp.async.wait_group 0;\n" ::)

#define MMA_BF16(ACC, A0, A1, A2, A3, B0, B1)                                  \
    asm volatile("mma.sync.aligned.m16n8k16.row.col.f32.bf16.bf16.f32 "        \
                 "{%0,%1,%2,%3}, {%4,%5,%6,%7}, {%8,%9}, {%0,%1,%2,%3};"       \
                 : "+f"(ACC[0]), "+f"(ACC[1]), "+f"(ACC[2]), "+f"(ACC[3])      \
                 : "r"(A0), "r"(A1), "r"(A2), "r"(A3), "r"(B0), "r"(B1))

#define LDMX4(F, ADDR)                                                          \
    asm volatile("ldmatrix.sync.aligned.m8n8.x4.shared.b16 {%0,%1,%2,%3}, [%4];"\
                 : "=r"(F[0]), "=r"(F[1]), "=r"(F[2]), "=r"(F[3]) : "r"(ADDR))
#define LDMX2T(F, ADDR)                                                         \
    asm volatile("ldmatrix.sync.aligned.m8n8.x2.trans.shared.b16 {%0,%1}, [%2];"\
                 : "=r"(F[0]), "=r"(F[1]) : "r"(ADDR))

// ---------------------------------------------------------------------------
// Forward GEMM, parity-folded: X[128perm, 512] = Fperm[128, 2048] @ {qe|qo}.
// Warp rows 0..63 (even k) use qe = q[l]+q[l+2048]; rows 64..127 use qo.
// 128x64 CTA tile, 8 warps 4x2 (32x32 each), K-chunk 32, split-K 4.
// ---------------------------------------------------------------------------
#define FTKC 32
#define FASTR 40                       // 32 + 8 pad (bf16 elems)
#define FATILE (128 * FASTR * 2)       // 10240
#define FBSTR 72
#define FBT (FTKC * FBSTR * 2)         // 4608
#define FBUF (2 * FATILE + 4 * FBT)    // 38912

__global__ __launch_bounds__(256, 2) void fwd_gemm(const float* __restrict__ Bf32) {
    constexpr int NCHUNK = (LH / RSPLIT) / FTKC;   // 16

    const int b = blockIdx.z;
    const int col0 = blockIdx.x * 64;
    const int kbeg = blockIdx.y * (LH / RSPLIT);
    const float* Bq = Bf32 + (size_t)b * (L_LEN * NC);
    float* Cb = g_Xpart + ((size_t)blockIdx.y * NB + b) * (128 * NC);

    extern __shared__ __align__(16) char smem[];
    const unsigned su = (unsigned)__cvta_generic_to_shared(smem);
    const int tid = threadIdx.x;
    const int lane = tid & 31, wid = tid >> 5;
    const int wm = wid & 3, wn = wid >> 2;
    const int sel = wm >> 1;          // 0: even-k rows -> qe,  1: odd -> qo

    float acc[2][4][4];
#pragma unroll
    for (int mi = 0; mi < 2; mi++)
#pragma unroll
        for (int ni = 0; ni < 4; ni++)
#pragma unroll
            for (int r = 0; r < 4; r++) acc[mi][ni][r] = 0.0f;

    auto prefetchA = [&](int ch) {
        const int k0 = kbeg + ch * FTKC;
        const unsigned base = su + (ch & 1) * FBUF;
#pragma unroll
        for (int i = 0; i < 2; i++) {             // 128 rows x 64B = 512 x 16B
            int idx = tid + i * 256;
            int r = idx >> 2, s8 = idx & 3;
            const size_t off = (size_t)r * LH + k0 + s8 * 8;
            CP_ASYNC16(base + r * (FASTR * 2) + s8 * 16, g_fb_h + off);
            CP_ASYNC16(base + FATILE + r * (FASTR * 2) + s8 * 16, g_fb_l + off);
        }
        CP_COMMIT();
    };

    float4 ra[2], rb[2];
    auto ldgB = [&](int ch) {
        const int k0 = kbeg + ch * FTKC;
#pragma unroll
        for (int i = 0; i < 2; i++) {             // 32 rows x 16 float4
            int idx = tid + i * 256;
            int r = idx >> 4, c4 = idx & 15;
            ra[i] = *(const float4*)(Bq + (size_t)(k0 + r) * NC + col0 + c4 * 4);
            rb[i] = *(const float4*)(Bq + (size_t)(k0 + r + LH) * NC + col0 + c4 * 4);
        }
    };
    auto stsB = [&](int ch) {
        char* base = smem + (ch & 1) * FBUF + 2 * FATILE;
#pragma unroll
        for (int i = 0; i < 2; i++) {
            int idx = tid + i * 256;
            int r = idx >> 4, c4 = idx & 15;
            const int off = r * (FBSTR * 2) + c4 * 8;
            float ev[4] = {ra[i].x + rb[i].x, ra[i].y + rb[i].y,
                           ra[i].z + rb[i].z, ra[i].w + rb[i].w};
            float ov[4] = {ra[i].x - rb[i].x, ra[i].y - rb[i].y,
                           ra[i].z - rb[i].z, ra[i].w - rb[i].w};
            __nv_bfloat16 h0, l0, h1, l1, h2, l2, h3, l3;
            split2(ev[0], h0, l0); split2(ev[1], h1, l1);
            split2(ev[2], h2, l2); split2(ev[3], h3, l3);
            ((__nv_bfloat162*)(base + off))[0] = __nv_bfloat162(h0, h1);
            ((__nv_bfloat162*)(base + off))[1] = __nv_bfloat162(h2, h3);
            ((__nv_bfloat162*)(base + FBT + off))[0] = __nv_bfloat162(l0, l1);
            ((__nv_bfloat162*)(base + FBT + off))[1] = __nv_bfloat162(l2, l3);
            split2(ov[0], h0, l0); split2(ov[1], h1, l1);
            split2(ov[2], h2, l2); split2(ov[3], h3, l3);
            ((__nv_bfloat162*)(base + 2 * FBT + off))[0] = __nv_bfloat162(h0, h1);
            ((__nv_bfloat162*)(base + 2 * FBT + off))[1] = __nv_bfloat162(h2, h3);
            ((__nv_bfloat162*)(base + 3 * FBT + off))[0] = __nv_bfloat162(l0, l1);
            ((__nv_bfloat162*)(base + 3 * FBT + off))[1] = __nv_bfloat162(l2, l3);
        }
    };

    ldgB(0);
    prefetchA(0);

    for (int it = 0; it < NCHUNK; it++) {
        stsB(it);
        if (it + 1 < NCHUNK) { ldgB(it + 1); prefetchA(it + 1); CP_WAIT1(); }
        else { CP_WAIT0(); }
        __syncthreads();

        const unsigned base = su + (it & 1) * FBUF;
        const unsigned bpar = base + 2 * FATILE + sel * (2 * FBT);
#pragma unroll
        for (int kstep = 0; kstep < 2; kstep++) {
            unsigned fah[2][4], fal[2][4], fb[4][2];
#pragma unroll
            for (int mi = 0; mi < 2; mi++) {
                unsigned addr = base +
                    (unsigned)((wm * 32 + mi * 16 + (lane & 15)) * (FASTR * 2) +
                               kstep * 32 + (lane >> 4) * 16);
                LDMX4(fah[mi], addr);
                LDMX4(fal[mi], addr + FATILE);
            }
            const unsigned brow = (unsigned)((kstep * 16 + (lane & 15)) * (FBSTR * 2) +
                                             (wn * 32) * 2);
#pragma unroll
            for (int ni = 0; ni < 4; ni++) LDMX2T(fb[ni], bpar + brow + ni * 16);
#pragma unroll
            for (int mi = 0; mi < 2; mi++)
#pragma unroll
                for (int ni = 0; ni < 4; ni++) {
                    MMA_BF16(acc[mi][ni], fah[mi][0], fah[mi][1], fah[mi][2], fah[mi][3],
                             fb[ni][0], fb[ni][1]);
                    MMA_BF16(acc[mi][ni], fal[mi][0], fal[mi][1], fal[mi][2], fal[mi][3],
                             fb[ni][0], fb[ni][1]);
                }
#pragma unroll
            for (int ni = 0; ni < 4; ni++) LDMX2T(fb[ni], bpar + FBT + brow + ni * 16);
#pragma unroll
            for (int mi = 0; mi < 2; mi++)
#pragma unroll
                for (int ni = 0; ni < 4; ni++)
                    MMA_BF16(acc[mi][ni], fah[mi][0], fah[mi][1], fah[mi][2], fah[mi][3],
                             fb[ni][0], fb[ni][1]);
        }
        __syncthreads();
    }

    const int g = lane >> 2, tig = lane & 3;
#pragma unroll
    for (int mi = 0; mi < 2; mi++)
#pragma unroll
        for (int ni = 0; ni < 4; ni++) {
            int r = wm * 32 + mi * 16 + g;
            int c = col0 + wn * 32 + ni * 8 + tig * 2;
            *(float2*)&Cb[(size_t)r * NC + c] = make_float2(acc[mi][ni][0], acc[mi][ni][1]);
            *(float2*)&Cb[(size_t)(r + 8) * NC + c] = make_float2(acc[mi][ni][2], acc[mi][ni][3]);
        }
}

// ---------------------------------------------------------------------------
// Inverse GEMM, parity-folded + B-resident. Y (128 x 64 hi/lo) in smem once.
// Per mb (128 l-rows of 2048): chunk c=0 -> acc_e (even cols), c=1 -> acc_o;
// epilogue writes y[l] = e+o and y[l+2048] = e-o. 2 mb per CTA, 4-deep pipe.
// ---------------------------------------------------------------------------
#define IBSTR 72
#define IB_MAT (128 * IBSTR * 2)          // 18432
#define IV_AOFF (2 * IB_MAT)
#define IV_ABUF (2 * IB_MAT)
#define IV_SMEM (IV_AOFF + 2 * IV_ABUF)   // 110592

__global__ __launch_bounds__(256, 2) void inv_gemm(float* __restrict__ Cext) {
    const int b = blockIdx.z;
    const int col0 = blockIdx.x * 64;
    const int m0 = blockIdx.y * 256;      // l-base within [0, 2048)
    const __nv_bfloat16* Bh = g_Y_h + (size_t)b * (128 * NC);
    const __nv_bfloat16* Bl = g_Y_l + (size_t)b * (128 * NC);
    float* Cb = Cext + (size_t)b * (L_LEN * NC);

    extern __shared__ __align__(16) char smem[];
    const unsigned su = (unsigned)__cvta_generic_to_shared(smem);
    const int tid = threadIdx.x;
    const int lane = tid & 31, wid = tid >> 5;
    const int wm = wid & 3, wn = wid >> 2;

#pragma unroll
    for (int i = 0; i < 4; i++) {          // Y hi/lo, all 128 perm rows
        int idx = tid + i * 256;
        int r = idx >> 3, s8 = idx & 7;
        const size_t off = (size_t)r * NC + col0 + s8 * 8;
        CP_ASYNC16(su + r * (IBSTR * 2) + s8 * 16, Bh + off);
        CP_ASYNC16(su + IB_MAT + r * (IBSTR * 2) + s8 * 16, Bl + off);
    }

    auto prefA = [&](int it) {             // it = mb*2 + c
        const int mb = it >> 1, c = it & 1;
        const unsigned base = su + IV_AOFF + (it & 1) * IV_ABUF;
#pragma unroll
        for (int i = 0; i < 4; i++) {
            int idx = tid + i * 256;
            int r = idx >> 3, s8 = idx & 7;
            const size_t off = (size_t)(m0 + mb * 128 + r) * 128 + c * 64 + s8 * 8;
            CP_ASYNC16(base + r * (IBSTR * 2) + s8 * 16, g_ib_h + off);
            CP_ASYNC16(base + IB_MAT + r * (IBSTR * 2) + s8 * 16, g_ib_l + off);
        }
        CP_COMMIT();
    };

    prefA(0);

    float acc[2][2][4][4];                 // [parity][mi][ni][frag]
#pragma unroll
    for (int p = 0; p < 2; p++)
#pragma unroll
        for (int mi = 0; mi < 2; mi++)
#pragma unroll
            for (int ni = 0; ni < 4; ni++)
#pragma unroll
                for (int r = 0; r < 4; r++) acc[p][mi][ni][r] = 0.0f;

    const int g = lane >> 2, tig = lane & 3;

    for (int it = 0; it < 4; it++) {
        if (it + 1 < 4) { prefA(it + 1); CP_WAIT1(); }
        else { CP_WAIT0(); }
        __syncthreads();

        const int c = it & 1;
        const unsigned abase = su + IV_AOFF + (it & 1) * IV_ABUF;
#pragma unroll
        for (int kstep = 0; kstep < 4; kstep++) {
            unsigned fah[2][4], fal[2][4], fb[4][2];
#pragma unroll
            for (int mi = 0; mi < 2; mi++) {
                unsigned addr = abase +
                    (unsigned)((wm * 32 + mi * 16 + (lane & 15)) * (IBSTR * 2) +
                               kstep * 32 + (lane >> 4) * 16);
                LDMX4(fah[mi], addr);
                LDMX4(fal[mi], addr + IB_MAT);
            }
            const unsigned brow = su +
                (unsigned)((c * 64 + kstep * 16 + (lane & 15)) * (IBSTR * 2) +
                           (wn * 32) * 2);
#pragma unroll
            for (int ni = 0; ni < 4; ni++) LDMX2T(fb[ni], brow + ni * 16);
#pragma unroll
            for (int mi = 0; mi < 2; mi++)
#pragma unroll
                for (int ni = 0; ni < 4; ni++) {
                    MMA_BF16(acc[c][mi][ni], fah[mi][0], fah[mi][1], fah[mi][2], fah[mi][3],
                             fb[ni][0], fb[ni][1]);
                    MMA_BF16(acc[c][mi][ni], fal[mi][0], fal[mi][1], fal[mi][2], fal[mi][3],
                             fb[ni][0], fb[ni][1]);
                }
#pragma unroll
            for (int ni = 0; ni < 4; ni++) LDMX2T(fb[ni], brow + IB_MAT + ni * 16);
#pragma unroll
            for (int mi = 0; mi < 2; mi++)
#pragma unroll
                for (int ni = 0; ni < 4; ni++)
                    MMA_BF16(acc[c][mi][ni], fah[mi][0], fah[mi][1], fah[mi][2], fah[mi][3],
                             fb[ni][0], fb[ni][1]);
        }

        if (c == 1) {                      // mb complete: combine + write both halves
            const int mb = it >> 1;
#pragma unroll
            for (int mi = 0; mi < 2; mi++)
#pragma unroll
                for (int ni = 0; ni < 4; ni++) {
                    int r = m0 + mb * 128 + wm * 32 + mi * 16 + g;
                    int cc = col0 + wn * 32 + ni * 8 + tig * 2;
                    float e0 = acc[0][mi][ni][0], o0 = acc[1][mi][ni][0];
                    float e1 = acc[0][mi][ni][1], o1 = acc[1][mi][ni][1];
                    float e2 = acc[0][mi][ni][2], o2 = acc[1][mi][ni][2];
                    float e3 = acc[0][mi][ni][3], o3 = acc[1][mi][ni][3];
                    *(float2*)&Cb[(size_t)r * NC + cc] = make_float2(e0 + o0, e1 + o1);
                    *(float2*)&Cb[(size_t)(r + 8) * NC + cc] = make_float2(e2 + o2, e3 + o3);
                    *(float2*)&Cb[(size_t)(r + LH) * NC + cc] = make_float2(e0 - o0, e1 - o1);
                    *(float2*)&Cb[(size_t)(r + LH + 8) * NC + cc] = make_float2(e2 - o2, e3 - o3);
#pragma unroll
                    for (int q = 0; q < 4; q++) {
                        acc[0][mi][ni][q] = 0.0f;
                        acc[1][mi][ni][q] = 0.0f;
                    }
                }
        }
        __syncthreads();
    }
}

// ---------------------------------------------------------------------------
// Split-K reduce + per-(k,h) complex mix; permuted row indexing:
// real row = (k&1)*64 + (k>>1), imag row = +32.
// ---------------------------------------------------------------------------
__global__ __launch_bounds__(512) void einsum_kernel(const float* __restrict__ Wr,
                                                     const float* __restrict__ Wi) {
    __shared__ float sWr[64][64];
    __shared__ float sWi[64][64];
    __shared__ float sXr[8][64];
    __shared__ float sXi[8][64];

    const int kh = blockIdx.x;
    const int k = kh >> 3;
    const int h = kh & 7;
    const int tid = threadIdx.x;
    const int base = ((k & 1) << 6) + (k >> 1);

    const float4* wr4 = (const float4*)(Wr + (size_t)kh * 4096);
    const float4* wi4 = (const float4*)(Wi + (size_t)kh * 4096);
    float4* sWr4 = (float4*)sWr;
    float4* sWi4 = (float4*)sWi;
#pragma unroll
    for (int e = 0; e < 2; e++) {
        sWr4[tid + e * 512] = wr4[tid + e * 512];
        sWi4[tid + e * 512] = wi4[tid + e * 512];
    }
    {
        const int b = tid >> 6, i = tid & 63;
        float sr = 0.f, si = 0.f;
        const float* p = g_Xpart + (size_t)b * (128 * NC) + (size_t)base * NC + h * 64 + i;
#pragma unroll
        for (int s = 0; s < RSPLIT; s++) {
            sr += p[0];
            si += p[32 * NC];
            p += (size_t)NB * 128 * NC;
        }
        sXr[b][i] = sr;
        sXi[b][i] = si;
    }
    __syncthreads();

    const int o = tid & 63;
    const int bb = tid >> 6;
    const float w = (k == 0 ? 1.0f : 2.0f) / (float)L_LEN;
    float ar = 0.f, ai = 0.f;
#pragma unroll
    for (int i = 0; i < 64; i++) {
        const float xr = sXr[bb][i], xi = sXi[bb][i];
        const float wrv = sWr[i][o], wiv = sWi[i][o];
        ar += xr * wrv - xi * wiv;
        ai += xr * wiv + xi * wrv;
    }
    const size_t pr = (size_t)bb * (128 * NC) + (size_t)base * NC + h * 64 + o;
    const size_t pi = pr + (size_t)32 * NC;
    __nv_bfloat16 hh, ll;
    split2(ar * w, hh, ll);
    g_Y_h[pr] = hh; g_Y_l[pr] = ll;
    split2(ai * w, hh, ll);
    g_Y_h[pi] = hh; g_Y_l[pi] = ll;
}

// ---------------------------------------------------------------------------
// inputs (metadata order): q, k, v, W_real, W_imag, mask
// ---------------------------------------------------------------------------
extern "C" void kernel_launch(void* const* d_in, const int* in_sizes, int n_in,
                              void* d_out, int out_size) {
    const float* q  = (const float*)d_in[0];
    const float* Wr = (const float*)d_in[3];
    const float* Wi = (const float*)d_in[4];
    float* out = (float*)d_out;

    static bool attr_done = false;
    if (!attr_done) {
        cudaFuncSetAttribute(fwd_gemm, cudaFuncAttributeMaxDynamicSharedMemorySize,
                             2 * FBUF);
        cudaFuncSetAttribute(inv_gemm, cudaFuncAttributeMaxDynamicSharedMemorySize,
                             IV_SMEM);
        attr_done = true;
    }

    init_kernel<<<(128 * LH + 255) / 256, 256>>>();
    fwd_gemm<<<dim3(8, RSPLIT, NB), 256, 2 * FBUF>>>(q);
    einsum_kernel<<<KF * NH, 512>>>(Wr, Wi);
    inv_gemm<<<dim3(8, LH / 256, NB), 256, IV_SMEM>>>(out);
}